// round 7
// baseline (speedup 1.0000x reference)
#include <cuda_runtime.h>
#include <cuda_bf16.h>
#include <cstdint>

// ---------------------------------------------------------------------------
// Problem constants
// ---------------------------------------------------------------------------
#define MAXN 50000
#define D_IN 128
#define D_OUT 128
#define D_NODEREP 134  // 128 + 6
#define DH 256
#define EPS 1e-5f

#define TILE_E 128
#define ETHREADS 256

// smem strides (floats) — conflict-free mma fragment LDS
#define S_H 132        // mod 32 = 4
#define S_WA 136       // 128-col weight chunks (mod 32 = 8)
#define S_WB 264       // 256-col weight chunks (mod 32 = 8)

// ---- edge kernel smem layout (floats) ----
#define HBUF_OFF 0
#define HBUF_FLOATS (TILE_E * S_H)             // 16896
#define TZ_OFF HBUF_FLOATS                     // featz / t-half / z overlay
#define TZ_FLOATS (TILE_E * S_H)               // 16896
#define WB_OFF (TZ_OFF + TZ_FLOATS)            // 33792
#define WB_BUF 4352                            // 32 rows * 136
#define E_SMEM_FLOATS (WB_OFF + 2 * WB_BUF)    // 42496 floats = 170 KB

// ---- node projection kernel ----
#define TILE_N 64
#define NPTHREADS 256
#define KPAD_P 144     // 134 padded to 16*9
#define NCH_P 9
#define S_P 164        // mod 32 = 4
#define NP_A_FLOATS (TILE_N * S_P)             // 10496
#define NP_WBUF 4224                           // 16 * 264
#define NP_SMEM_FLOATS (NP_A_FLOATS + 2 * NP_WBUF)  // 18944 floats = 75.8 KB

// Scratch (static device globals: no allocation allowed)
__device__ float g_agg[(size_t)MAXN * D_IN];
__device__ float g_den[MAXN];
__device__ float g_P[(size_t)MAXN * 256];      // [N][Pa(128) | Pb(128)]

// ---------------------------------------------------------------------------
// helpers
// ---------------------------------------------------------------------------
__device__ __forceinline__ unsigned f2tf(float f) {
    unsigned u;
    asm("cvt.rna.tf32.f32 %0, %1;" : "=r"(u) : "f"(f));
    return u;
}

__device__ __forceinline__ void mma_tf32(float* c, const unsigned* a,
                                         unsigned b0, unsigned b1) {
    asm volatile(
        "mma.sync.aligned.m16n8k8.row.col.f32.tf32.tf32.f32 "
        "{%0,%1,%2,%3},{%4,%5,%6,%7},{%8,%9},{%0,%1,%2,%3};\n"
        : "+f"(c[0]), "+f"(c[1]), "+f"(c[2]), "+f"(c[3])
        : "r"(a[0]), "r"(a[1]), "r"(a[2]), "r"(a[3]), "r"(b0), "r"(b1));
}

__device__ __forceinline__ void cp16(float* dst_smem, const float* src, bool pred) {
    unsigned d = (unsigned)__cvta_generic_to_shared(dst_smem);
    int sz = pred ? 16 : 0;
    asm volatile("cp.async.cg.shared.global [%0], [%1], 16, %2;\n"
                 :: "r"(d), "l"(src), "r"(sz));
}
__device__ __forceinline__ void cp_commit() {
    asm volatile("cp.async.commit_group;\n");
}
template <int N>
__device__ __forceinline__ void cp_wait() {
    asm volatile("cp.async.wait_group %0;\n" :: "n"(N));
}

// ---------------------------------------------------------------------------
// Kernel 1: zero the scratch
// ---------------------------------------------------------------------------
__global__ void zero_kernel(int N) {
    int idx = blockIdx.x * blockDim.x + threadIdx.x;
    int total = N * D_IN;
    if (idx < total) g_agg[idx] = 0.f;
    if (idx < N) g_den[idx] = 0.f;
}

// ---------------------------------------------------------------------------
// Kernel 2: masked scatter-add aggregation (warp per edge, float4 atomics)
// ---------------------------------------------------------------------------
__global__ void agg_kernel(const float* __restrict__ edge_attr,
                           const float* __restrict__ mask,
                           const int* __restrict__ edge_index, int E) {
    int w = (blockIdx.x * blockDim.x + threadIdx.x) >> 5;
    int lane = threadIdx.x & 31;
    if (w >= E) return;
    float m = mask[w];
    if (m == 0.f) return;
    int col = edge_index[E + w];
    const float4* a = (const float4*)(edge_attr + (size_t)w * D_IN);
    float4* dst = (float4*)(g_agg + (size_t)col * D_IN);
    float4 v = a[lane];
    v.x *= m; v.y *= m; v.z *= m; v.w *= m;
    atomicAdd(dst + lane, v);
    if (lane == 0) atomicAdd(g_den + col, m);
}

// ---------------------------------------------------------------------------
// Kernel 3: node projection  P = node_rep @ [We_a | We_b]   (N x 256)
// Also materializes node_rep into out_node.
// ---------------------------------------------------------------------------
__global__ void __launch_bounds__(NPTHREADS, 2)
nodeproj_kernel(const float* __restrict__ x,
                const float* __restrict__ We,
                float* __restrict__ out_node, int N) {
    extern __shared__ float sm[];
    float* A = sm;
    float* wb = sm + NP_A_FLOATS;
    __shared__ float rden_s[TILE_N];

    const int tid = threadIdx.x;
    const int lane = tid & 31;
    const int wid = tid >> 5;
    const int n0blk = blockIdx.x * TILE_N;

    const int m0 = 16 * (wid >> 1);
    const int n0 = 128 * (wid & 1);
    const int r0 = lane >> 2;
    const int qk = lane & 3;
    const int cb = 2 * qk;

    auto issue_w = [&](int ch, int stage) {  // 16 rows x 256 cols (Wea|Web)
        float* dst = wb + stage * NP_WBUF;
        int kb = ch * 16;
#pragma unroll
        for (int j = 0; j < 4; j++) {
            int i = tid + j * NPTHREADS;
            int r = i >> 6;
            int c4 = (i & 63) * 4;
            int k = kb + r;
            const float* src = (c4 < 128)
                ? We + (size_t)k * D_OUT + c4
                : We + (size_t)(D_NODEREP + k) * D_OUT + (c4 - 128);
            cp16(dst + r * S_WB + c4, src, k < D_NODEREP);
        }
        cp_commit();
    };

    issue_w(0, 0);

    if (tid < TILE_N) {
        int n = n0blk + tid;
        float d = (n < N) ? g_den[n] : 0.f;
        rden_s[tid] = 1.0f / (d + 1.0f);
    }
    __syncthreads();

    for (int idx = tid; idx < TILE_N * KPAD_P; idx += NPTHREADS) {
        int e = idx / KPAD_P;
        int k = idx - e * KPAD_P;
        int n = n0blk + e;
        float v = 0.f;
        if (n < N && k < D_NODEREP) {
            if (k < D_IN)
                v = g_agg[(size_t)n * D_IN + k] * rden_s[e];
            else
                v = x[n * 6 + (k - D_IN)];
            out_node[(size_t)n * D_NODEREP + k] = v;
        }
        A[e * S_P + k] = v;
    }

    float acc[16][4];
#pragma unroll
    for (int nt = 0; nt < 16; nt++)
#pragma unroll
        for (int q = 0; q < 4; q++) acc[nt][q] = 0.f;

    for (int ch = 0; ch < NCH_P; ch++) {
        cp_wait<0>();
        __syncthreads();
        if (ch + 1 < NCH_P) issue_w(ch + 1, (ch + 1) & 1);
        const float* cur = wb + (ch & 1) * NP_WBUF;
#pragma unroll
        for (int ks = 0; ks < 2; ks++) {
            int k0 = ch * 16 + ks * 8;
            const float* ap = A + (m0 + r0) * S_P + k0 + qk;
            unsigned a[4];
            a[0] = f2tf(ap[0]);
            a[1] = f2tf(ap[8 * S_P]);
            a[2] = f2tf(ap[4]);
            a[3] = f2tf(ap[8 * S_P + 4]);
#pragma unroll
            for (int nt = 0; nt < 16; nt++) {
                const float* bp = cur + (ks * 8 + qk) * S_WB + n0 + 8 * nt + r0;
                mma_tf32(acc[nt], a, __float_as_uint(bp[0]),
                         __float_as_uint(bp[4 * S_WB]));
            }
        }
    }

#pragma unroll
    for (int nt = 0; nt < 16; nt++) {
        int col = n0 + 8 * nt + cb;
#pragma unroll
        for (int q = 0; q < 4; q++) {
            int rr = m0 + r0 + (q >> 1) * 8;
            int cc = col + (q & 1);
            int n = n0blk + rr;
            if (n < N) g_P[(size_t)n * 256 + cc] = acc[nt][q];
        }
    }
}

// ---------------------------------------------------------------------------
// Kernel 4: fused edge MLP.
// 128 edges/block, 256 threads (8 warps, warp tile m32 x n64), 1 block/SM.
// Pipeline order: wait -> barrier -> issue(ch+1) -> compute(ch)  (race-free).
// ---------------------------------------------------------------------------
__global__ void __launch_bounds__(ETHREADS, 1)
edge_kernel(const float* __restrict__ edge_attr,
            const int* __restrict__ edge_index,
            const float* __restrict__ We, const float* __restrict__ bE,
            const float* __restrict__ W1, const float* __restrict__ b1,
            const float* __restrict__ W2, const float* __restrict__ b2,
            const float* __restrict__ g1, const float* __restrict__ be1,
            const float* __restrict__ g2, const float* __restrict__ be2,
            float* __restrict__ out, int E) {
    extern __shared__ float sm[];
    float* hbuf = sm + HBUF_OFF;
    float* tz = sm + TZ_OFF;    // featz -> t-half -> z overlay
    float* wb = sm + WB_OFF;
    __shared__ int rows_s[TILE_E], cols_s[TILE_E];

    const int tid = threadIdx.x;
    const int lane = tid & 31;
    const int wid = tid >> 5;
    const int e0 = blockIdx.x * TILE_E;

    const int m0 = 32 * (wid & 3);    // 0,32,64,96
    const int n064 = 64 * (wid >> 2); // 0 or 64
    const int r0 = lane >> 2;
    const int qk = lane & 3;
    const int cb = 2 * qk;

    auto issue_wec = [&](int ch, int stage) {  // We_c rows 268+ch*32.., 32x128
        float* dst = wb + stage * WB_BUF;
        int kb = ch * 32;
#pragma unroll
        for (int j = 0; j < 4; j++) {
            int i = tid + j * ETHREADS;
            int r = i >> 5, c4 = (i & 31) * 4;
            cp16(dst + r * S_WA + c4,
                 We + (size_t)(2 * D_NODEREP + kb + r) * D_OUT + c4, true);
        }
        cp_commit();
    };
    auto issue_w1h = [&](int hf, int ch, int stage) {  // W1 16 x 128 (half hf)
        float* dst = wb + stage * WB_BUF;
        int kb = ch * 16;
#pragma unroll
        for (int j = 0; j < 2; j++) {
            int i = tid + j * ETHREADS;
            int r = i >> 5, c4 = (i & 31) * 4;
            cp16(dst + r * S_WA + c4,
                 W1 + (size_t)(kb + r) * DH + hf * 128 + c4, true);
        }
        cp_commit();
    };
    auto issue_w2h = [&](int hf, int ch, int stage) {  // W2 32 x 128 (rows half)
        float* dst = wb + stage * WB_BUF;
        int kb = hf * 128 + ch * 32;
#pragma unroll
        for (int j = 0; j < 4; j++) {
            int i = tid + j * ETHREADS;
            int r = i >> 5, c4 = (i & 31) * 4;
            cp16(dst + r * S_WA + c4, W2 + (size_t)(kb + r) * D_OUT + c4, true);
        }
        cp_commit();
    };

    if (tid < TILE_E) {
        int eg = e0 + tid;
        rows_s[tid] = (eg < E) ? edge_index[eg] : 0;
        cols_s[tid] = (eg < E) ? edge_index[E + eg] : 0;
    }

    issue_wec(0, 0);

    // edge_attr tile -> tz (featz), float4 coalesced
    for (int idx = tid; idx < TILE_E * 32; idx += ETHREADS) {
        int e = idx >> 5;
        int c4 = (idx & 31) * 4;
        int eg = e0 + e;
        float4 v = make_float4(0.f, 0.f, 0.f, 0.f);
        if (eg < E) v = *(const float4*)(edge_attr + (size_t)eg * D_IN + c4);
        *(float4*)(tz + e * S_H + c4) = v;
    }
    __syncthreads();  // rows_s/cols_s ready

    // hbuf = Pa[row] + Pb[col]  (float4 gather from L2-resident P)
    for (int idx = tid; idx < TILE_E * 32; idx += ETHREADS) {
        int e = idx >> 5;
        int c4 = (idx & 31) * 4;
        float4 pa = *(const float4*)(g_P + (size_t)rows_s[e] * 256 + c4);
        float4 pb = *(const float4*)(g_P + (size_t)cols_s[e] * 256 + 128 + c4);
        pa.x += pb.x; pa.y += pb.y; pa.z += pb.z; pa.w += pb.w;
        *(float4*)(hbuf + e * S_H + c4) = pa;
    }

    // ================= GEMM1: featz[128,128] @ We_c[128,128] =============
    {
        float acc[2][8][4];
#pragma unroll
        for (int mt = 0; mt < 2; mt++)
#pragma unroll
            for (int nt = 0; nt < 8; nt++)
#pragma unroll
                for (int q = 0; q < 4; q++) acc[mt][nt][q] = 0.f;

        const int NCH = 4;
        for (int ch = 0; ch < NCH; ch++) {
            cp_wait<0>();
            __syncthreads();
            if (ch + 1 < NCH) issue_wec(ch + 1, (ch + 1) & 1);
            const float* cur = wb + (ch & 1) * WB_BUF;
#pragma unroll
            for (int ks = 0; ks < 4; ks++) {
                int k0 = ch * 32 + ks * 8;
                unsigned a[2][4];
#pragma unroll
                for (int mt = 0; mt < 2; mt++) {
                    const float* ap = tz + (m0 + 16 * mt + r0) * S_H + k0 + qk;
                    a[mt][0] = f2tf(ap[0]);
                    a[mt][1] = f2tf(ap[8 * S_H]);
                    a[mt][2] = f2tf(ap[4]);
                    a[mt][3] = f2tf(ap[8 * S_H + 4]);
                }
#pragma unroll
                for (int nt = 0; nt < 8; nt++) {
                    const float* bp = cur + (ks * 8 + qk) * S_WA + n064 + 8 * nt + r0;
                    unsigned b0 = __float_as_uint(bp[0]);
                    unsigned b1 = __float_as_uint(bp[4 * S_WA]);
                    mma_tf32(acc[0][nt], a[0], b0, b1);
                    mma_tf32(acc[1][nt], a[1], b0, b1);
                }
            }
        }

        // h += acc + bE + edge_attr residual (featz)
#pragma unroll
        for (int mt = 0; mt < 2; mt++)
#pragma unroll
            for (int nt = 0; nt < 8; nt++) {
                int col = n064 + 8 * nt + cb;
#pragma unroll
                for (int q = 0; q < 4; q++) {
                    int rr = m0 + 16 * mt + r0 + (q >> 1) * 8;
                    int cc = col + (q & 1);
                    hbuf[rr * S_H + cc] +=
                        acc[mt][nt][q] + __ldg(&bE[cc]) + tz[rr * S_H + cc];
                }
            }
    }
    __syncthreads();

    // ---------------- LayerNorm1 (in place on hbuf) ----------------
    for (int r = wid; r < TILE_E; r += 8) {
        float v[4], s = 0.f, s2 = 0.f;
#pragma unroll
        for (int q = 0; q < 4; q++) {
            v[q] = hbuf[r * S_H + lane + 32 * q];
            s += v[q];
            s2 += v[q] * v[q];
        }
#pragma unroll
        for (int off = 16; off > 0; off >>= 1) {
            s += __shfl_xor_sync(0xFFFFFFFF, s, off);
            s2 += __shfl_xor_sync(0xFFFFFFFF, s2, off);
        }
        float mu = s * (1.f / 128.f);
        float var = s2 * (1.f / 128.f) - mu * mu;
        float rinv = rsqrtf(var + EPS);
#pragma unroll
        for (int q = 0; q < 4; q++) {
            int c = lane + 32 * q;
            hbuf[r * S_H + c] = (v[q] - mu) * rinv * __ldg(&g1[c]) + __ldg(&be1[c]);
        }
    }
    __syncthreads();

    // ============ GEMM2+GEMM3 in two 128-halves, acc3 persistent =========
    float acc3[2][8][4];
#pragma unroll
    for (int mt = 0; mt < 2; mt++)
#pragma unroll
        for (int nt = 0; nt < 8; nt++)
#pragma unroll
            for (int q = 0; q < 4; q++) acc3[mt][nt][q] = 0.f;

#pragma unroll 1
    for (int hf = 0; hf < 2; hf++) {
        // ---- GEMM2 half: t_half = relu(h @ W1[:, hf*128:+128] + b1h) ----
        {
            float acc2[2][8][4];
#pragma unroll
            for (int mt = 0; mt < 2; mt++)
#pragma unroll
                for (int nt = 0; nt < 8; nt++)
#pragma unroll
                    for (int q = 0; q < 4; q++) acc2[mt][nt][q] = 0.f;

            issue_w1h(hf, 0, 0);
            const int NCH = 8;
            for (int ch = 0; ch < NCH; ch++) {
                cp_wait<0>();
                __syncthreads();
                if (ch + 1 < NCH) issue_w1h(hf, ch + 1, (ch + 1) & 1);
                const float* cur = wb + (ch & 1) * WB_BUF;
#pragma unroll
                for (int ks = 0; ks < 2; ks++) {
                    int k0 = ch * 16 + ks * 8;
                    unsigned a[2][4];
#pragma unroll
                    for (int mt = 0; mt < 2; mt++) {
                        const float* ap = hbuf + (m0 + 16 * mt + r0) * S_H + k0 + qk;
                        a[mt][0] = f2tf(ap[0]);
                        a[mt][1] = f2tf(ap[8 * S_H]);
                        a[mt][2] = f2tf(ap[4]);
                        a[mt][3] = f2tf(ap[8 * S_H + 4]);
                    }
#pragma unroll
                    for (int nt = 0; nt < 8; nt++) {
                        const float* bp = cur + (ks * 8 + qk) * S_WA + n064 + 8 * nt + r0;
                        unsigned b0 = __float_as_uint(bp[0]);
                        unsigned b1 = __float_as_uint(bp[4 * S_WA]);
                        mma_tf32(acc2[0][nt], a[0], b0, b1);
                        mma_tf32(acc2[1][nt], a[1], b0, b1);
                    }
                }
            }
            __syncthreads();  // last wb reads done; tz free to write

            // t_half -> tz (tf32-rounded bits, GEMM3 A operand)
#pragma unroll
            for (int mt = 0; mt < 2; mt++)
#pragma unroll
                for (int nt = 0; nt < 8; nt++) {
                    int col = n064 + 8 * nt + cb;
#pragma unroll
                    for (int q = 0; q < 4; q++) {
                        int rr = m0 + 16 * mt + r0 + (q >> 1) * 8;
                        int cc = col + (q & 1);
                        float t = fmaxf(acc2[mt][nt][q] + __ldg(&b1[hf * 128 + cc]), 0.f);
                        tz[rr * S_H + cc] = __uint_as_float(f2tf(t));
                    }
                }
        }
        __syncthreads();

        // ---- GEMM3 half: acc3 += t_half @ W2[hf*128:+128, :] ----
        {
            issue_w2h(hf, 0, 0);
            const int NCH = 4;
            for (int ch = 0; ch < NCH; ch++) {
                cp_wait<0>();
                __syncthreads();
                if (ch + 1 < NCH) issue_w2h(hf, ch + 1, (ch + 1) & 1);
                const float* cur = wb + (ch & 1) * WB_BUF;
#pragma unroll
                for (int ks = 0; ks < 4; ks++) {
                    int k0 = ch * 32 + ks * 8;
                    unsigned a[2][4];
#pragma unroll
                    for (int mt = 0; mt < 2; mt++) {
                        const float* ap = tz + (m0 + 16 * mt + r0) * S_H + k0 + qk;
                        a[mt][0] = __float_as_uint(ap[0]);
                        a[mt][1] = __float_as_uint(ap[8 * S_H]);
                        a[mt][2] = __float_as_uint(ap[4]);
                        a[mt][3] = __float_as_uint(ap[8 * S_H + 4]);
                    }
#pragma unroll
                    for (int nt = 0; nt < 8; nt++) {
                        const float* bp = cur + (ks * 8 + qk) * S_WA + n064 + 8 * nt + r0;
                        unsigned b0 = __float_as_uint(bp[0]);
                        unsigned b1 = __float_as_uint(bp[4 * S_WA]);
                        mma_tf32(acc3[0][nt], a[0], b0, b1);
                        mma_tf32(acc3[1][nt], a[1], b0, b1);
                    }
                }
            }
        }
        __syncthreads();  // tz reads done before next hf overwrites it
    }

    // z = acc3 + b2 + h  -> tz (t-half dead)
#pragma unroll
    for (int mt = 0; mt < 2; mt++)
#pragma unroll
        for (int nt = 0; nt < 8; nt++) {
            int col = n064 + 8 * nt + cb;
#pragma unroll
            for (int q = 0; q < 4; q++) {
                int rr = m0 + 16 * mt + r0 + (q >> 1) * 8;
                int cc = col + (q & 1);
                tz[rr * S_H + cc] = acc3[mt][nt][q] + __ldg(&b2[cc]) + hbuf[rr * S_H + cc];
            }
        }
    __syncthreads();

    // ---------------- LayerNorm2 -> global out ----------------
    for (int r = wid; r < TILE_E; r += 8) {
        int eg = e0 + r;
        float v[4], s = 0.f, s2 = 0.f;
#pragma unroll
        for (int q = 0; q < 4; q++) {
            v[q] = tz[r * S_H + lane + 32 * q];
            s += v[q];
            s2 += v[q] * v[q];
        }
#pragma unroll
        for (int off = 16; off > 0; off >>= 1) {
            s += __shfl_xor_sync(0xFFFFFFFF, s, off);
            s2 += __shfl_xor_sync(0xFFFFFFFF, s2, off);
        }
        float mu = s * (1.f / 128.f);
        float var = s2 * (1.f / 128.f) - mu * mu;
        float rinv = rsqrtf(var + EPS);
        if (eg < E) {
#pragma unroll
            for (int q = 0; q < 4; q++) {
                int c = lane + 32 * q;
                out[(size_t)eg * D_OUT + c] = (v[q] - mu) * rinv * __ldg(&g2[c]) + __ldg(&be2[c]);
            }
        }
    }
}

// ---------------------------------------------------------------------------
// launch
// ---------------------------------------------------------------------------
extern "C" void kernel_launch(void* const* d_in, const int* in_sizes, int n_in,
                              void* d_out, int out_size) {
    const void* p[16];
    int sz[16];
    int m = 0;
    for (int i = 0; i < n_in && m < 16; i++) {
        if (in_sizes[i] == 1) continue;
        p[m] = d_in[i];
        sz[m] = in_sizes[i];
        m++;
    }
    const float* x          = (const float*)p[0];
    const int*   edge_index = (const int*)p[1];
    const float* edge_attr  = (const float*)p[2];
    const float* mask       = (const float*)p[3];
    const float* We         = (const float*)p[4];
    const float* bE         = (const float*)p[5];
    const float* W1         = (const float*)p[6];
    const float* b1         = (const float*)p[7];
    const float* W2         = (const float*)p[8];
    const float* b2         = (const float*)p[9];
    const float* g1         = (const float*)p[10];
    const float* be1        = (const float*)p[11];
    const float* g2         = (const float*)p[12];
    const float* be2        = (const float*)p[13];

    const int N = sz[0] / 6;
    const int E = sz[3];

    float* out_node = (float*)d_out;                     // [N,134]
    float* out_edge = out_node + (size_t)N * D_NODEREP;  // [E,128]

    {
        int total = N * D_IN;
        zero_kernel<<<(total + 255) / 256, 256>>>(N);
    }
    {
        agg_kernel<<<(E + 7) / 8, 256>>>(edge_attr, mask, edge_index, E);
    }
    {
        const int smem = NP_SMEM_FLOATS * (int)sizeof(float);
        cudaFuncSetAttribute(nodeproj_kernel, cudaFuncAttributeMaxDynamicSharedMemorySize, smem);
        int blocks = (N + TILE_N - 1) / TILE_N;
        nodeproj_kernel<<<blocks, NPTHREADS, smem>>>(x, We, out_node, N);
    }
    {
        const int smem = E_SMEM_FLOATS * (int)sizeof(float);
        cudaFuncSetAttribute(edge_kernel, cudaFuncAttributeMaxDynamicSharedMemorySize, smem);
        int blocks = (E + TILE_E - 1) / TILE_E;
        edge_kernel<<<blocks, ETHREADS, smem>>>(edge_attr, edge_index,
                                                We, bE, W1, b1, W2, b2,
                                                g1, be1, g2, be2, out_edge, E);
    }
}

// round 8
// speedup vs baseline: 1.3044x; 1.3044x over previous
#include <cuda_runtime.h>
#include <cuda_bf16.h>
#include <cstdint>

// ---------------------------------------------------------------------------
// Problem constants
// ---------------------------------------------------------------------------
#define MAXN 50000
#define D_IN 128
#define D_OUT 128
#define D_NODEREP 134  // 128 + 6
#define DH 256
#define EPS 1e-5f

#define TILE_E 64
#define ETHREADS 256

// smem strides (floats) — conflict-free mma fragment LDS
#define S_H 132        // mod 32 = 4
#define S_WA 136       // 128-col weight chunks (mod 32 = 8)
#define S_WB 264       // 256-col weight chunks (mod 32 = 8)

// ---- edge kernel smem layout (floats) ----
#define HBUF_OFF 0
#define HBUF_FLOATS (TILE_E * S_H)             // 8448
#define TZ_OFF HBUF_FLOATS                     // featz / t-half / z overlay
#define TZ_FLOATS (TILE_E * S_H)               // 8448
#define WB_OFF (TZ_OFF + TZ_FLOATS)            // 16896
#define WB_BUF 4352                            // 32 rows * 136
#define E_SMEM_FLOATS (WB_OFF + 2 * WB_BUF)    // 25600 floats = 102.4 KB

// ---- node projection kernel ----
#define TILE_N 64
#define NPTHREADS 256
#define KPAD_P 144     // 134 padded to 16*9
#define NCH_P 9
#define S_P 164        // mod 32 = 4
#define NP_A_FLOATS (TILE_N * S_P)             // 10496
#define NP_WBUF 4224                           // 16 * 264
#define NP_SMEM_FLOATS (NP_A_FLOATS + 2 * NP_WBUF)  // 18944 floats = 75.8 KB

// Scratch (static device globals: no allocation allowed)
__device__ float g_agg[(size_t)MAXN * D_IN];
__device__ float g_den[MAXN];
__device__ float g_P[(size_t)MAXN * 256];      // [N][Pa(128) | Pb(128)]

// ---------------------------------------------------------------------------
// helpers
// ---------------------------------------------------------------------------
__device__ __forceinline__ unsigned f2tf(float f) {
    unsigned u;
    asm("cvt.rna.tf32.f32 %0, %1;" : "=r"(u) : "f"(f));
    return u;
}

__device__ __forceinline__ void mma_tf32(float* c, const unsigned* a,
                                         unsigned b0, unsigned b1) {
    asm volatile(
        "mma.sync.aligned.m16n8k8.row.col.f32.tf32.tf32.f32 "
        "{%0,%1,%2,%3},{%4,%5,%6,%7},{%8,%9},{%0,%1,%2,%3};\n"
        : "+f"(c[0]), "+f"(c[1]), "+f"(c[2]), "+f"(c[3])
        : "r"(a[0]), "r"(a[1]), "r"(a[2]), "r"(a[3]), "r"(b0), "r"(b1));
}

__device__ __forceinline__ void cp16(float* dst_smem, const float* src, bool pred) {
    unsigned d = (unsigned)__cvta_generic_to_shared(dst_smem);
    int sz = pred ? 16 : 0;
    asm volatile("cp.async.cg.shared.global [%0], [%1], 16, %2;\n"
                 :: "r"(d), "l"(src), "r"(sz));
}
__device__ __forceinline__ void cp_commit() {
    asm volatile("cp.async.commit_group;\n");
}
template <int N>
__device__ __forceinline__ void cp_wait() {
    asm volatile("cp.async.wait_group %0;\n" :: "n"(N));
}

// ---------------------------------------------------------------------------
// Kernel 1: zero the scratch
// ---------------------------------------------------------------------------
__global__ void zero_kernel(int N) {
    int idx = blockIdx.x * blockDim.x + threadIdx.x;
    int total = N * D_IN;
    if (idx < total) g_agg[idx] = 0.f;
    if (idx < N) g_den[idx] = 0.f;
}

// ---------------------------------------------------------------------------
// Kernel 2: masked scatter-add aggregation (warp per edge, float4 atomics)
// ---------------------------------------------------------------------------
__global__ void agg_kernel(const float* __restrict__ edge_attr,
                           const float* __restrict__ mask,
                           const int* __restrict__ edge_index, int E) {
    int w = (blockIdx.x * blockDim.x + threadIdx.x) >> 5;
    int lane = threadIdx.x & 31;
    if (w >= E) return;
    float m = mask[w];
    if (m == 0.f) return;
    int col = edge_index[E + w];
    const float4* a = (const float4*)(edge_attr + (size_t)w * D_IN);
    float4* dst = (float4*)(g_agg + (size_t)col * D_IN);
    float4 v = a[lane];
    v.x *= m; v.y *= m; v.z *= m; v.w *= m;
    atomicAdd(dst + lane, v);
    if (lane == 0) atomicAdd(g_den + col, m);
}

// ---------------------------------------------------------------------------
// Kernel 3: node projection  P = node_rep @ [We_a | We_b]   (N x 256)
// Also materializes node_rep into out_node.
// ---------------------------------------------------------------------------
__global__ void __launch_bounds__(NPTHREADS, 2)
nodeproj_kernel(const float* __restrict__ x,
                const float* __restrict__ We,
                float* __restrict__ out_node, int N) {
    extern __shared__ float sm[];
    float* A = sm;
    float* wb = sm + NP_A_FLOATS;
    __shared__ float rden_s[TILE_N];

    const int tid = threadIdx.x;
    const int lane = tid & 31;
    const int wid = tid >> 5;
    const int n0blk = blockIdx.x * TILE_N;

    const int m0 = 16 * (wid >> 1);
    const int n0 = 128 * (wid & 1);
    const int r0 = lane >> 2;
    const int qk = lane & 3;
    const int cb = 2 * qk;

    auto issue_w = [&](int ch, int stage) {  // 16 rows x 256 cols (Wea|Web)
        float* dst = wb + stage * NP_WBUF;
        int kb = ch * 16;
#pragma unroll
        for (int j = 0; j < 4; j++) {
            int i = tid + j * NPTHREADS;
            int r = i >> 6;
            int c4 = (i & 63) * 4;
            int k = kb + r;
            const float* src = (c4 < 128)
                ? We + (size_t)k * D_OUT + c4
                : We + (size_t)(D_NODEREP + k) * D_OUT + (c4 - 128);
            cp16(dst + r * S_WB + c4, src, k < D_NODEREP);
        }
        cp_commit();
    };

    issue_w(0, 0);

    if (tid < TILE_N) {
        int n = n0blk + tid;
        float d = (n < N) ? g_den[n] : 0.f;
        rden_s[tid] = 1.0f / (d + 1.0f);
    }
    __syncthreads();

    for (int idx = tid; idx < TILE_N * KPAD_P; idx += NPTHREADS) {
        int e = idx / KPAD_P;
        int k = idx - e * KPAD_P;
        int n = n0blk + e;
        float v = 0.f;
        if (n < N && k < D_NODEREP) {
            if (k < D_IN)
                v = g_agg[(size_t)n * D_IN + k] * rden_s[e];
            else
                v = x[n * 6 + (k - D_IN)];
            out_node[(size_t)n * D_NODEREP + k] = v;
        }
        A[e * S_P + k] = v;
    }

    float acc[16][4];
#pragma unroll
    for (int nt = 0; nt < 16; nt++)
#pragma unroll
        for (int q = 0; q < 4; q++) acc[nt][q] = 0.f;

    for (int ch = 0; ch < NCH_P; ch++) {
        cp_wait<0>();
        __syncthreads();
        if (ch + 1 < NCH_P) issue_w(ch + 1, (ch + 1) & 1);
        const float* cur = wb + (ch & 1) * NP_WBUF;
#pragma unroll
        for (int ks = 0; ks < 2; ks++) {
            int k0 = ch * 16 + ks * 8;
            const float* ap = A + (m0 + r0) * S_P + k0 + qk;
            unsigned a[4];
            a[0] = f2tf(ap[0]);
            a[1] = f2tf(ap[8 * S_P]);
            a[2] = f2tf(ap[4]);
            a[3] = f2tf(ap[8 * S_P + 4]);
#pragma unroll
            for (int nt = 0; nt < 16; nt++) {
                const float* bp = cur + (ks * 8 + qk) * S_WB + n0 + 8 * nt + r0;
                mma_tf32(acc[nt], a, __float_as_uint(bp[0]),
                         __float_as_uint(bp[4 * S_WB]));
            }
        }
    }

#pragma unroll
    for (int nt = 0; nt < 16; nt++) {
        int col = n0 + 8 * nt + cb;
#pragma unroll
        for (int q = 0; q < 4; q++) {
            int rr = m0 + r0 + (q >> 1) * 8;
            int cc = col + (q & 1);
            int n = n0blk + rr;
            if (n < N) g_P[(size_t)n * 256 + cc] = acc[nt][q];
        }
    }
}

// ---------------------------------------------------------------------------
// Kernel 4: fused edge MLP.
// 64 edges/block, 256 threads (8 warps, warp tile m32 x n32), 2 blocks/SM.
// Warp grid: m0 = 32*(wid&1) in {0,32}; n032 = 32*(wid>>1) in {0,32,64,96}.
// Pipeline order: wait -> barrier -> issue(ch+1) -> compute(ch)  (race-free).
// ---------------------------------------------------------------------------
__global__ void __launch_bounds__(ETHREADS, 2)
edge_kernel(const float* __restrict__ edge_attr,
            const int* __restrict__ edge_index,
            const float* __restrict__ We, const float* __restrict__ bE,
            const float* __restrict__ W1, const float* __restrict__ b1,
            const float* __restrict__ W2, const float* __restrict__ b2,
            const float* __restrict__ g1, const float* __restrict__ be1,
            const float* __restrict__ g2, const float* __restrict__ be2,
            float* __restrict__ out, int E) {
    extern __shared__ float sm[];
    float* hbuf = sm + HBUF_OFF;
    float* tz = sm + TZ_OFF;    // featz -> t-half -> z overlay
    float* wb = sm + WB_OFF;
    __shared__ int rows_s[TILE_E], cols_s[TILE_E];

    const int tid = threadIdx.x;
    const int lane = tid & 31;
    const int wid = tid >> 5;
    const int e0 = blockIdx.x * TILE_E;

    const int m0 = 32 * (wid & 1);     // 0 or 32
    const int n032 = 32 * (wid >> 1);  // 0,32,64,96
    const int r0 = lane >> 2;
    const int qk = lane & 3;
    const int cb = 2 * qk;

    auto issue_wec = [&](int ch, int stage) {  // We_c rows 268+ch*32.., 32x128
        float* dst = wb + stage * WB_BUF;
        int kb = ch * 32;
#pragma unroll
        for (int j = 0; j < 4; j++) {
            int i = tid + j * ETHREADS;
            int r = i >> 5, c4 = (i & 31) * 4;
            cp16(dst + r * S_WA + c4,
                 We + (size_t)(2 * D_NODEREP + kb + r) * D_OUT + c4, true);
        }
        cp_commit();
    };
    auto issue_w1h = [&](int hf, int ch, int stage) {  // W1 16 x 128 (half hf)
        float* dst = wb + stage * WB_BUF;
        int kb = ch * 16;
#pragma unroll
        for (int j = 0; j < 2; j++) {
            int i = tid + j * ETHREADS;
            int r = i >> 5, c4 = (i & 31) * 4;
            cp16(dst + r * S_WA + c4,
                 W1 + (size_t)(kb + r) * DH + hf * 128 + c4, true);
        }
        cp_commit();
    };
    auto issue_w2h = [&](int hf, int ch, int stage) {  // W2 32 x 128 (rows half)
        float* dst = wb + stage * WB_BUF;
        int kb = hf * 128 + ch * 32;
#pragma unroll
        for (int j = 0; j < 4; j++) {
            int i = tid + j * ETHREADS;
            int r = i >> 5, c4 = (i & 31) * 4;
            cp16(dst + r * S_WA + c4, W2 + (size_t)(kb + r) * D_OUT + c4, true);
        }
        cp_commit();
    };

    if (tid < TILE_E) {
        int eg = e0 + tid;
        rows_s[tid] = (eg < E) ? edge_index[eg] : 0;
        cols_s[tid] = (eg < E) ? edge_index[E + eg] : 0;
    }

    issue_wec(0, 0);

    // edge_attr tile -> tz (featz), float4 coalesced
    for (int idx = tid; idx < TILE_E * 32; idx += ETHREADS) {
        int e = idx >> 5;
        int c4 = (idx & 31) * 4;
        int eg = e0 + e;
        float4 v = make_float4(0.f, 0.f, 0.f, 0.f);
        if (eg < E) v = *(const float4*)(edge_attr + (size_t)eg * D_IN + c4);
        *(float4*)(tz + e * S_H + c4) = v;
    }
    __syncthreads();  // rows_s/cols_s ready

    // hbuf = Pa[row] + Pb[col]  (float4 gather from L2-resident P)
    for (int idx = tid; idx < TILE_E * 32; idx += ETHREADS) {
        int e = idx >> 5;
        int c4 = (idx & 31) * 4;
        float4 pa = *(const float4*)(g_P + (size_t)rows_s[e] * 256 + c4);
        float4 pb = *(const float4*)(g_P + (size_t)cols_s[e] * 256 + 128 + c4);
        pa.x += pb.x; pa.y += pb.y; pa.z += pb.z; pa.w += pb.w;
        *(float4*)(hbuf + e * S_H + c4) = pa;
    }

    // ================= GEMM1: featz[64,128] @ We_c[128,128] ==============
    {
        float acc[2][4][4];
#pragma unroll
        for (int mt = 0; mt < 2; mt++)
#pragma unroll
            for (int nt = 0; nt < 4; nt++)
#pragma unroll
                for (int q = 0; q < 4; q++) acc[mt][nt][q] = 0.f;

        const int NCH = 4;
        for (int ch = 0; ch < NCH; ch++) {
            cp_wait<0>();
            __syncthreads();
            if (ch + 1 < NCH) issue_wec(ch + 1, (ch + 1) & 1);
            const float* cur = wb + (ch & 1) * WB_BUF;
#pragma unroll
            for (int ks = 0; ks < 4; ks++) {
                int k0 = ch * 32 + ks * 8;
                unsigned a[2][4];
#pragma unroll
                for (int mt = 0; mt < 2; mt++) {
                    const float* ap = tz + (m0 + 16 * mt + r0) * S_H + k0 + qk;
                    a[mt][0] = f2tf(ap[0]);
                    a[mt][1] = f2tf(ap[8 * S_H]);
                    a[mt][2] = f2tf(ap[4]);
                    a[mt][3] = f2tf(ap[8 * S_H + 4]);
                }
#pragma unroll
                for (int nt = 0; nt < 4; nt++) {
                    const float* bp = cur + (ks * 8 + qk) * S_WA + n032 + 8 * nt + r0;
                    unsigned b0 = __float_as_uint(bp[0]);
                    unsigned b1 = __float_as_uint(bp[4 * S_WA]);
                    mma_tf32(acc[0][nt], a[0], b0, b1);
                    mma_tf32(acc[1][nt], a[1], b0, b1);
                }
            }
        }

        // h += acc + bE + edge_attr residual (featz)
#pragma unroll
        for (int mt = 0; mt < 2; mt++)
#pragma unroll
            for (int nt = 0; nt < 4; nt++) {
                int col = n032 + 8 * nt + cb;
#pragma unroll
                for (int q = 0; q < 4; q++) {
                    int rr = m0 + 16 * mt + r0 + (q >> 1) * 8;
                    int cc = col + (q & 1);
                    hbuf[rr * S_H + cc] +=
                        acc[mt][nt][q] + __ldg(&bE[cc]) + tz[rr * S_H + cc];
                }
            }
    }
    __syncthreads();

    // ---------------- LayerNorm1 (in place on hbuf) ----------------
    for (int r = wid; r < TILE_E; r += 8) {
        float v[4], s = 0.f, s2 = 0.f;
#pragma unroll
        for (int q = 0; q < 4; q++) {
            v[q] = hbuf[r * S_H + lane + 32 * q];
            s += v[q];
            s2 += v[q] * v[q];
        }
#pragma unroll
        for (int off = 16; off > 0; off >>= 1) {
            s += __shfl_xor_sync(0xFFFFFFFF, s, off);
            s2 += __shfl_xor_sync(0xFFFFFFFF, s2, off);
        }
        float mu = s * (1.f / 128.f);
        float var = s2 * (1.f / 128.f) - mu * mu;
        float rinv = rsqrtf(var + EPS);
#pragma unroll
        for (int q = 0; q < 4; q++) {
            int c = lane + 32 * q;
            hbuf[r * S_H + c] = (v[q] - mu) * rinv * __ldg(&g1[c]) + __ldg(&be1[c]);
        }
    }
    __syncthreads();

    // ============ GEMM2+GEMM3 in two 128-halves, acc3 persistent =========
    float acc3[2][4][4];
#pragma unroll
    for (int mt = 0; mt < 2; mt++)
#pragma unroll
        for (int nt = 0; nt < 4; nt++)
#pragma unroll
            for (int q = 0; q < 4; q++) acc3[mt][nt][q] = 0.f;

#pragma unroll 1
    for (int hf = 0; hf < 2; hf++) {
        // ---- GEMM2 half: t_half = relu(h @ W1[:, hf*128:+128] + b1h) ----
        {
            float acc2[2][4][4];
#pragma unroll
            for (int mt = 0; mt < 2; mt++)
#pragma unroll
                for (int nt = 0; nt < 4; nt++)
#pragma unroll
                    for (int q = 0; q < 4; q++) acc2[mt][nt][q] = 0.f;

            issue_w1h(hf, 0, 0);
            const int NCH = 8;
            for (int ch = 0; ch < NCH; ch++) {
                cp_wait<0>();
                __syncthreads();
                if (ch + 1 < NCH) issue_w1h(hf, ch + 1, (ch + 1) & 1);
                const float* cur = wb + (ch & 1) * WB_BUF;
#pragma unroll
                for (int ks = 0; ks < 2; ks++) {
                    int k0 = ch * 16 + ks * 8;
                    unsigned a[2][4];
#pragma unroll
                    for (int mt = 0; mt < 2; mt++) {
                        const float* ap = hbuf + (m0 + 16 * mt + r0) * S_H + k0 + qk;
                        a[mt][0] = f2tf(ap[0]);
                        a[mt][1] = f2tf(ap[8 * S_H]);
                        a[mt][2] = f2tf(ap[4]);
                        a[mt][3] = f2tf(ap[8 * S_H + 4]);
                    }
#pragma unroll
                    for (int nt = 0; nt < 4; nt++) {
                        const float* bp = cur + (ks * 8 + qk) * S_WA + n032 + 8 * nt + r0;
                        unsigned b0 = __float_as_uint(bp[0]);
                        unsigned b1 = __float_as_uint(bp[4 * S_WA]);
                        mma_tf32(acc2[0][nt], a[0], b0, b1);
                        mma_tf32(acc2[1][nt], a[1], b0, b1);
                    }
                }
            }
            __syncthreads();  // last wb reads done; tz free to write

            // t_half -> tz (tf32-rounded bits, GEMM3 A operand)
#pragma unroll
            for (int mt = 0; mt < 2; mt++)
#pragma unroll
                for (int nt = 0; nt < 4; nt++) {
                    int col = n032 + 8 * nt + cb;
#pragma unroll
                    for (int q = 0; q < 4; q++) {
                        int rr = m0 + 16 * mt + r0 + (q >> 1) * 8;
                        int cc = col + (q & 1);
                        float t = fmaxf(acc2[mt][nt][q] + __ldg(&b1[hf * 128 + cc]), 0.f);
                        tz[rr * S_H + cc] = __uint_as_float(f2tf(t));
                    }
                }
        }
        __syncthreads();

        // ---- GEMM3 half: acc3 += t_half @ W2[hf*128:+128, :] ----
        {
            issue_w2h(hf, 0, 0);
            const int NCH = 4;
            for (int ch = 0; ch < NCH; ch++) {
                cp_wait<0>();
                __syncthreads();
                if (ch + 1 < NCH) issue_w2h(hf, ch + 1, (ch + 1) & 1);
                const float* cur = wb + (ch & 1) * WB_BUF;
#pragma unroll
                for (int ks = 0; ks < 4; ks++) {
                    int k0 = ch * 32 + ks * 8;
                    unsigned a[2][4];
#pragma unroll
                    for (int mt = 0; mt < 2; mt++) {
                        const float* ap = tz + (m0 + 16 * mt + r0) * S_H + k0 + qk;
                        a[mt][0] = __float_as_uint(ap[0]);
                        a[mt][1] = __float_as_uint(ap[8 * S_H]);
                        a[mt][2] = __float_as_uint(ap[4]);
                        a[mt][3] = __float_as_uint(ap[8 * S_H + 4]);
                    }
#pragma unroll
                    for (int nt = 0; nt < 4; nt++) {
                        const float* bp = cur + (ks * 8 + qk) * S_WA + n032 + 8 * nt + r0;
                        unsigned b0 = __float_as_uint(bp[0]);
                        unsigned b1 = __float_as_uint(bp[4 * S_WA]);
                        mma_tf32(acc3[0][nt], a[0], b0, b1);
                        mma_tf32(acc3[1][nt], a[1], b0, b1);
                    }
                }
            }
        }
        __syncthreads();  // tz reads done before next hf overwrites it
    }

    // z = acc3 + b2 + h  -> tz (t-half dead)
#pragma unroll
    for (int mt = 0; mt < 2; mt++)
#pragma unroll
        for (int nt = 0; nt < 4; nt++) {
            int col = n032 + 8 * nt + cb;
#pragma unroll
            for (int q = 0; q < 4; q++) {
                int rr = m0 + 16 * mt + r0 + (q >> 1) * 8;
                int cc = col + (q & 1);
                tz[rr * S_H + cc] = acc3[mt][nt][q] + __ldg(&b2[cc]) + hbuf[rr * S_H + cc];
            }
        }
    __syncthreads();

    // ---------------- LayerNorm2 -> global out ----------------
    for (int r = wid; r < TILE_E; r += 8) {
        int eg = e0 + r;
        float v[4], s = 0.f, s2 = 0.f;
#pragma unroll
        for (int q = 0; q < 4; q++) {
            v[q] = tz[r * S_H + lane + 32 * q];
            s += v[q];
            s2 += v[q] * v[q];
        }
#pragma unroll
        for (int off = 16; off > 0; off >>= 1) {
            s += __shfl_xor_sync(0xFFFFFFFF, s, off);
            s2 += __shfl_xor_sync(0xFFFFFFFF, s2, off);
        }
        float mu = s * (1.f / 128.f);
        float var = s2 * (1.f / 128.f) - mu * mu;
        float rinv = rsqrtf(var + EPS);
        if (eg < E) {
#pragma unroll
            for (int q = 0; q < 4; q++) {
                int c = lane + 32 * q;
                out[(size_t)eg * D_OUT + c] = (v[q] - mu) * rinv * __ldg(&g2[c]) + __ldg(&be2[c]);
            }
        }
    }
}

// ---------------------------------------------------------------------------
// launch
// ---------------------------------------------------------------------------
extern "C" void kernel_launch(void* const* d_in, const int* in_sizes, int n_in,
                              void* d_out, int out_size) {
    const void* p[16];
    int sz[16];
    int m = 0;
    for (int i = 0; i < n_in && m < 16; i++) {
        if (in_sizes[i] == 1) continue;
        p[m] = d_in[i];
        sz[m] = in_sizes[i];
        m++;
    }
    const float* x          = (const float*)p[0];
    const int*   edge_index = (const int*)p[1];
    const float* edge_attr  = (const float*)p[2];
    const float* mask       = (const float*)p[3];
    const float* We         = (const float*)p[4];
    const float* bE         = (const float*)p[5];
    const float* W1         = (const float*)p[6];
    const float* b1         = (const float*)p[7];
    const float* W2         = (const float*)p[8];
    const float* b2         = (const float*)p[9];
    const float* g1         = (const float*)p[10];
    const float* be1        = (const float*)p[11];
    const float* g2         = (const float*)p[12];
    const float* be2        = (const float*)p[13];

    const int N = sz[0] / 6;
    const int E = sz[3];

    float* out_node = (float*)d_out;                     // [N,134]
    float* out_edge = out_node + (size_t)N * D_NODEREP;  // [E,128]

    {
        int total = N * D_IN;
        zero_kernel<<<(total + 255) / 256, 256>>>(N);
    }
    {
        agg_kernel<<<(E + 7) / 8, 256>>>(edge_attr, mask, edge_index, E);
    }
    {
        const int smem = NP_SMEM_FLOATS * (int)sizeof(float);
        cudaFuncSetAttribute(nodeproj_kernel, cudaFuncAttributeMaxDynamicSharedMemorySize, smem);
        int blocks = (N + TILE_N - 1) / TILE_N;
        nodeproj_kernel<<<blocks, NPTHREADS, smem>>>(x, We, out_node, N);
    }
    {
        const int smem = E_SMEM_FLOATS * (int)sizeof(float);
        cudaFuncSetAttribute(edge_kernel, cudaFuncAttributeMaxDynamicSharedMemorySize, smem);
        int blocks = (E + TILE_E - 1) / TILE_E;
        edge_kernel<<<blocks, ETHREADS, smem>>>(edge_attr, edge_index,
                                                We, bE, W1, b1, W2, b2,
                                                g1, be1, g2, be2, out_edge, E);
    }
}

// round 9
// speedup vs baseline: 1.3224x; 1.0138x over previous
#include <cuda_runtime.h>
#include <cuda_bf16.h>
#include <cstdint>

// ---------------------------------------------------------------------------
// Problem constants
// ---------------------------------------------------------------------------
#define MAXN 50000
#define D_IN 128
#define D_OUT 128
#define D_NODEREP 134  // 128 + 6
#define DH 256
#define EPS 1e-5f

#define TILE_E 64
#define ETHREADS 256

// smem strides (floats) — conflict-free mma fragment LDS
#define S_H 132        // mod 32 = 4
#define S_WA 136       // 128-col weight chunks (mod 32 = 8)
#define S_WB 264       // 256-col weight chunks (mod 32 = 8)

// ---- edge kernel smem layout (floats) ----
#define HBUF_OFF 0
#define HBUF_FLOATS (TILE_E * S_H)             // 8448
#define TZ_OFF HBUF_FLOATS                     // featz / t-half / z overlay
#define TZ_FLOATS (TILE_E * S_H)               // 8448
#define WB_OFF (TZ_OFF + TZ_FLOATS)            // 16896
#define WB_SLOT 2176                           // 16 rows * 136
#define E_SMEM_FLOATS (WB_OFF + 4 * WB_SLOT)   // 25600 floats = 102.4 KB

// ---- node projection kernel ----
#define TILE_N 64
#define NPTHREADS 256
#define KPAD_P 144     // 134 padded to 16*9
#define NCH_P 9
#define S_P 164        // mod 32 = 4
#define NP_A_FLOATS (TILE_N * S_P)             // 10496
#define NP_WBUF 4224                           // 16 * 264
#define NP_SMEM_FLOATS (NP_A_FLOATS + 2 * NP_WBUF)  // 18944 floats = 75.8 KB

// Scratch (static device globals: no allocation allowed)
__device__ float g_agg[(size_t)MAXN * D_IN];
__device__ float g_den[MAXN];
__device__ float g_P[(size_t)MAXN * 256];      // [N][Pa(128) | Pb(128)]

// ---------------------------------------------------------------------------
// helpers
// ---------------------------------------------------------------------------
__device__ __forceinline__ unsigned f2tf(float f) {
    unsigned u;
    asm("cvt.rna.tf32.f32 %0, %1;" : "=r"(u) : "f"(f));
    return u;
}

__device__ __forceinline__ void mma_tf32(float* c, const unsigned* a,
                                         unsigned b0, unsigned b1) {
    asm volatile(
        "mma.sync.aligned.m16n8k8.row.col.f32.tf32.tf32.f32 "
        "{%0,%1,%2,%3},{%4,%5,%6,%7},{%8,%9},{%0,%1,%2,%3};\n"
        : "+f"(c[0]), "+f"(c[1]), "+f"(c[2]), "+f"(c[3])
        : "r"(a[0]), "r"(a[1]), "r"(a[2]), "r"(a[3]), "r"(b0), "r"(b1));
}

__device__ __forceinline__ void cp16(float* dst_smem, const float* src, bool pred) {
    unsigned d = (unsigned)__cvta_generic_to_shared(dst_smem);
    int sz = pred ? 16 : 0;
    asm volatile("cp.async.cg.shared.global [%0], [%1], 16, %2;\n"
                 :: "r"(d), "l"(src), "r"(sz));
}
__device__ __forceinline__ void cp_commit() {
    asm volatile("cp.async.commit_group;\n");
}
template <int N>
__device__ __forceinline__ void cp_wait() {
    asm volatile("cp.async.wait_group %0;\n" :: "n"(N));
}

// ---------------------------------------------------------------------------
// Kernel 1: zero the scratch
// ---------------------------------------------------------------------------
__global__ void zero_kernel(int N) {
    int idx = blockIdx.x * blockDim.x + threadIdx.x;
    int total = N * D_IN;
    if (idx < total) g_agg[idx] = 0.f;
    if (idx < N) g_den[idx] = 0.f;
}

// ---------------------------------------------------------------------------
// Kernel 2: masked scatter-add aggregation (warp per edge, float4 atomics)
// ---------------------------------------------------------------------------
__global__ void agg_kernel(const float* __restrict__ edge_attr,
                           const float* __restrict__ mask,
                           const int* __restrict__ edge_index, int E) {
    int w = (blockIdx.x * blockDim.x + threadIdx.x) >> 5;
    int lane = threadIdx.x & 31;
    if (w >= E) return;
    float m = mask[w];
    if (m == 0.f) return;
    int col = edge_index[E + w];
    const float4* a = (const float4*)(edge_attr + (size_t)w * D_IN);
    float4* dst = (float4*)(g_agg + (size_t)col * D_IN);
    float4 v = a[lane];
    v.x *= m; v.y *= m; v.z *= m; v.w *= m;
    atomicAdd(dst + lane, v);
    if (lane == 0) atomicAdd(g_den + col, m);
}

// ---------------------------------------------------------------------------
// Kernel 3: node projection  P = node_rep @ [We_a | We_b]   (N x 256)
// Also materializes node_rep into out_node.
// ---------------------------------------------------------------------------
__global__ void __launch_bounds__(NPTHREADS, 2)
nodeproj_kernel(const float* __restrict__ x,
                const float* __restrict__ We,
                float* __restrict__ out_node, int N) {
    extern __shared__ float sm[];
    float* A = sm;
    float* wb = sm + NP_A_FLOATS;
    __shared__ float rden_s[TILE_N];

    const int tid = threadIdx.x;
    const int lane = tid & 31;
    const int wid = tid >> 5;
    const int n0blk = blockIdx.x * TILE_N;

    const int m0 = 16 * (wid >> 1);
    const int n0 = 128 * (wid & 1);
    const int r0 = lane >> 2;
    const int qk = lane & 3;
    const int cb = 2 * qk;

    auto issue_w = [&](int ch, int stage) {  // 16 rows x 256 cols (Wea|Web)
        float* dst = wb + stage * NP_WBUF;
        int kb = ch * 16;
#pragma unroll
        for (int j = 0; j < 4; j++) {
            int i = tid + j * NPTHREADS;
            int r = i >> 6;
            int c4 = (i & 63) * 4;
            int k = kb + r;
            const float* src = (c4 < 128)
                ? We + (size_t)k * D_OUT + c4
                : We + (size_t)(D_NODEREP + k) * D_OUT + (c4 - 128);
            cp16(dst + r * S_WB + c4, src, k < D_NODEREP);
        }
        cp_commit();
    };

    issue_w(0, 0);

    if (tid < TILE_N) {
        int n = n0blk + tid;
        float d = (n < N) ? g_den[n] : 0.f;
        rden_s[tid] = 1.0f / (d + 1.0f);
    }
    __syncthreads();

    for (int idx = tid; idx < TILE_N * KPAD_P; idx += NPTHREADS) {
        int e = idx / KPAD_P;
        int k = idx - e * KPAD_P;
        int n = n0blk + e;
        float v = 0.f;
        if (n < N && k < D_NODEREP) {
            if (k < D_IN)
                v = g_agg[(size_t)n * D_IN + k] * rden_s[e];
            else
                v = x[n * 6 + (k - D_IN)];
            out_node[(size_t)n * D_NODEREP + k] = v;
        }
        A[e * S_P + k] = v;
    }

    float acc[16][4];
#pragma unroll
    for (int nt = 0; nt < 16; nt++)
#pragma unroll
        for (int q = 0; q < 4; q++) acc[nt][q] = 0.f;

    for (int ch = 0; ch < NCH_P; ch++) {
        cp_wait<0>();
        __syncthreads();
        if (ch + 1 < NCH_P) issue_w(ch + 1, (ch + 1) & 1);
        const float* cur = wb + (ch & 1) * NP_WBUF;
#pragma unroll
        for (int ks = 0; ks < 2; ks++) {
            int k0 = ch * 16 + ks * 8;
            const float* ap = A + (m0 + r0) * S_P + k0 + qk;
            unsigned a[4];
            a[0] = f2tf(ap[0]);
            a[1] = f2tf(ap[8 * S_P]);
            a[2] = f2tf(ap[4]);
            a[3] = f2tf(ap[8 * S_P + 4]);
#pragma unroll
            for (int nt = 0; nt < 16; nt++) {
                const float* bp = cur + (ks * 8 + qk) * S_WB + n0 + 8 * nt + r0;
                mma_tf32(acc[nt], a, __float_as_uint(bp[0]),
                         __float_as_uint(bp[4 * S_WB]));
            }
        }
    }

#pragma unroll
    for (int nt = 0; nt < 16; nt++) {
        int col = n0 + 8 * nt + cb;
#pragma unroll
        for (int q = 0; q < 4; q++) {
            int rr = m0 + r0 + (q >> 1) * 8;
            int cc = col + (q & 1);
            int n = n0blk + rr;
            if (n < N) g_P[(size_t)n * 256 + cc] = acc[nt][q];
        }
    }
}

// ---------------------------------------------------------------------------
// Kernel 4: fused edge MLP.
// 64 edges/block, 256 threads (8 warps, warp tile m32 x n32), 2 blocks/SM.
// Weight ring: 4 slots x 16 rows, depth-3 cp.async prefetch.
// Race-free ordering: wait -> barrier -> compute(ch) -> issue(ch+3).
//   (slot (ch+3)%4 was last read at iter ch-1; every thread passed this
//    iteration's barrier, hence finished iter ch-1's reads.)
// ---------------------------------------------------------------------------
__global__ void __launch_bounds__(ETHREADS, 2)
edge_kernel(const float* __restrict__ edge_attr,
            const int* __restrict__ edge_index,
            const float* __restrict__ We, const float* __restrict__ bE,
            const float* __restrict__ W1, const float* __restrict__ b1,
            const float* __restrict__ W2, const float* __restrict__ b2,
            const float* __restrict__ g1, const float* __restrict__ be1,
            const float* __restrict__ g2, const float* __restrict__ be2,
            float* __restrict__ out, int E) {
    extern __shared__ float sm[];
    float* hbuf = sm + HBUF_OFF;
    float* tz = sm + TZ_OFF;    // featz -> t-half -> z overlay
    float* wb = sm + WB_OFF;
    __shared__ int rows_s[TILE_E], cols_s[TILE_E];

    const int tid = threadIdx.x;
    const int lane = tid & 31;
    const int wid = tid >> 5;
    const int e0 = blockIdx.x * TILE_E;

    const int m0 = 32 * (wid & 1);     // 0 or 32
    const int n032 = 32 * (wid >> 1);  // 0,32,64,96
    const int r0 = lane >> 2;
    const int qk = lane & 3;
    const int cb = 2 * qk;

    // 16-row x 128-col chunk loaders (512 cp16 = 2 per thread)
    auto issue_wec = [&](int ch, int slot) {  // We_c rows 268+16ch..
        float* dst = wb + slot * WB_SLOT;
        int kb = ch * 16;
#pragma unroll
        for (int j = 0; j < 2; j++) {
            int i = tid + j * ETHREADS;
            int r = i >> 5, c4 = (i & 31) * 4;
            cp16(dst + r * S_WA + c4,
                 We + (size_t)(2 * D_NODEREP + kb + r) * D_OUT + c4, true);
        }
        cp_commit();
    };
    auto issue_w1h = [&](int hf, int ch, int slot) {  // W1 16 x 128 (col half)
        float* dst = wb + slot * WB_SLOT;
        int kb = ch * 16;
#pragma unroll
        for (int j = 0; j < 2; j++) {
            int i = tid + j * ETHREADS;
            int r = i >> 5, c4 = (i & 31) * 4;
            cp16(dst + r * S_WA + c4,
                 W1 + (size_t)(kb + r) * DH + hf * 128 + c4, true);
        }
        cp_commit();
    };
    auto issue_w2h = [&](int hf, int ch, int slot) {  // W2 16 x 128 (row half)
        float* dst = wb + slot * WB_SLOT;
        int kb = hf * 128 + ch * 16;
#pragma unroll
        for (int j = 0; j < 2; j++) {
            int i = tid + j * ETHREADS;
            int r = i >> 5, c4 = (i & 31) * 4;
            cp16(dst + r * S_WA + c4, W2 + (size_t)(kb + r) * D_OUT + c4, true);
        }
        cp_commit();
    };

    if (tid < TILE_E) {
        int eg = e0 + tid;
        rows_s[tid] = (eg < E) ? edge_index[eg] : 0;
        cols_s[tid] = (eg < E) ? edge_index[E + eg] : 0;
    }

    // GEMM1 prologue (depth 3) — overlaps the gathers below
    issue_wec(0, 0);
    issue_wec(1, 1);
    issue_wec(2, 2);

    // edge_attr tile -> tz (featz), float4 coalesced, PRE-ROUNDED to tf32
    // (same bits the per-kstep cvt produced; only the residual add sees the
    //  rounded value — tiny extra error, big alu-pipe saving)
    for (int idx = tid; idx < TILE_E * 32; idx += ETHREADS) {
        int e = idx >> 5;
        int c4 = (idx & 31) * 4;
        int eg = e0 + e;
        float4 v = make_float4(0.f, 0.f, 0.f, 0.f);
        if (eg < E) v = *(const float4*)(edge_attr + (size_t)eg * D_IN + c4);
        v.x = __uint_as_float(f2tf(v.x));
        v.y = __uint_as_float(f2tf(v.y));
        v.z = __uint_as_float(f2tf(v.z));
        v.w = __uint_as_float(f2tf(v.w));
        *(float4*)(tz + e * S_H + c4) = v;
    }
    __syncthreads();  // rows_s/cols_s ready

    // hbuf = Pa[row] + Pb[col]  (float4 gather from L2-resident P, fp32)
    for (int idx = tid; idx < TILE_E * 32; idx += ETHREADS) {
        int e = idx >> 5;
        int c4 = (idx & 31) * 4;
        float4 pa = *(const float4*)(g_P + (size_t)rows_s[e] * 256 + c4);
        float4 pb = *(const float4*)(g_P + (size_t)cols_s[e] * 256 + 128 + c4);
        pa.x += pb.x; pa.y += pb.y; pa.z += pb.z; pa.w += pb.w;
        *(float4*)(hbuf + e * S_H + c4) = pa;
    }

    // ================= GEMM1: featz[64,128] @ We_c[128,128] ==============
    {
        float acc[2][4][4];
#pragma unroll
        for (int mt = 0; mt < 2; mt++)
#pragma unroll
            for (int nt = 0; nt < 4; nt++)
#pragma unroll
                for (int q = 0; q < 4; q++) acc[mt][nt][q] = 0.f;

        const int NCH = 8;
        for (int ch = 0; ch < NCH; ch++) {
            if (ch < NCH - 2) cp_wait<2>();
            else if (ch == NCH - 2) cp_wait<1>();
            else cp_wait<0>();
            __syncthreads();
            const float* cur = wb + (ch & 3) * WB_SLOT;
#pragma unroll
            for (int ks = 0; ks < 2; ks++) {
                int k0 = ch * 16 + ks * 8;
                unsigned a[2][4];
#pragma unroll
                for (int mt = 0; mt < 2; mt++) {
                    const float* ap = tz + (m0 + 16 * mt + r0) * S_H + k0 + qk;
                    a[mt][0] = __float_as_uint(ap[0]);
                    a[mt][1] = __float_as_uint(ap[8 * S_H]);
                    a[mt][2] = __float_as_uint(ap[4]);
                    a[mt][3] = __float_as_uint(ap[8 * S_H + 4]);
                }
#pragma unroll
                for (int nt = 0; nt < 4; nt++) {
                    const float* bp = cur + (ks * 8 + qk) * S_WA + n032 + 8 * nt + r0;
                    unsigned b0 = __float_as_uint(bp[0]);
                    unsigned b1 = __float_as_uint(bp[4 * S_WA]);
                    mma_tf32(acc[0][nt], a[0], b0, b1);
                    mma_tf32(acc[1][nt], a[1], b0, b1);
                }
            }
            if (ch + 3 < NCH) issue_wec(ch + 3, (ch + 3) & 3);
        }

        // h += acc + bE + edge_attr residual (featz)
#pragma unroll
        for (int mt = 0; mt < 2; mt++)
#pragma unroll
            for (int nt = 0; nt < 4; nt++) {
                int col = n032 + 8 * nt + cb;
#pragma unroll
                for (int q = 0; q < 4; q++) {
                    int rr = m0 + 16 * mt + r0 + (q >> 1) * 8;
                    int cc = col + (q & 1);
                    hbuf[rr * S_H + cc] +=
                        acc[mt][nt][q] + __ldg(&bE[cc]) + tz[rr * S_H + cc];
                }
            }
    }
    __syncthreads();

    // hoist GEMM2(hf=0) prologue — copies land while LN1 runs
    issue_w1h(0, 0, 0);
    issue_w1h(0, 1, 1);
    issue_w1h(0, 2, 2);

    // ---------------- LayerNorm1 (stats on fp32, store tf32-rounded) -----
    for (int r = wid; r < TILE_E; r += 8) {
        float v[4], s = 0.f, s2 = 0.f;
#pragma unroll
        for (int q = 0; q < 4; q++) {
            v[q] = hbuf[r * S_H + lane + 32 * q];
            s += v[q];
            s2 += v[q] * v[q];
        }
#pragma unroll
        for (int off = 16; off > 0; off >>= 1) {
            s += __shfl_xor_sync(0xFFFFFFFF, s, off);
            s2 += __shfl_xor_sync(0xFFFFFFFF, s2, off);
        }
        float mu = s * (1.f / 128.f);
        float var = s2 * (1.f / 128.f) - mu * mu;
        float rinv = rsqrtf(var + EPS);
#pragma unroll
        for (int q = 0; q < 4; q++) {
            int c = lane + 32 * q;
            float hv = (v[q] - mu) * rinv * __ldg(&g1[c]) + __ldg(&be1[c]);
            hbuf[r * S_H + c] = __uint_as_float(f2tf(hv));
        }
    }
    __syncthreads();

    // ============ GEMM2+GEMM3 in two 128-halves, acc3 persistent =========
    float acc3[2][4][4];
#pragma unroll
    for (int mt = 0; mt < 2; mt++)
#pragma unroll
        for (int nt = 0; nt < 4; nt++)
#pragma unroll
            for (int q = 0; q < 4; q++) acc3[mt][nt][q] = 0.f;

#pragma unroll 1
    for (int hf = 0; hf < 2; hf++) {
        // ---- GEMM2 half: t_half = relu(h @ W1[:, hf*128:+128] + b1h) ----
        {
            float acc2[2][4][4];
#pragma unroll
            for (int mt = 0; mt < 2; mt++)
#pragma unroll
                for (int nt = 0; nt < 4; nt++)
#pragma unroll
                    for (int q = 0; q < 4; q++) acc2[mt][nt][q] = 0.f;

            if (hf) {  // hf=0 prologue was hoisted before LN1
                issue_w1h(hf, 0, 0);
                issue_w1h(hf, 1, 1);
                issue_w1h(hf, 2, 2);
            }
            const int NCH = 8;
            for (int ch = 0; ch < NCH; ch++) {
                if (ch < NCH - 2) cp_wait<2>();
                else if (ch == NCH - 2) cp_wait<1>();
                else cp_wait<0>();
                __syncthreads();
                const float* cur = wb + (ch & 3) * WB_SLOT;
#pragma unroll
                for (int ks = 0; ks < 2; ks++) {
                    int k0 = ch * 16 + ks * 8;
                    unsigned a[2][4];
#pragma unroll
                    for (int mt = 0; mt < 2; mt++) {
                        const float* ap = hbuf + (m0 + 16 * mt + r0) * S_H + k0 + qk;
                        a[mt][0] = __float_as_uint(ap[0]);
                        a[mt][1] = __float_as_uint(ap[8 * S_H]);
                        a[mt][2] = __float_as_uint(ap[4]);
                        a[mt][3] = __float_as_uint(ap[8 * S_H + 4]);
                    }
#pragma unroll
                    for (int nt = 0; nt < 4; nt++) {
                        const float* bp = cur + (ks * 8 + qk) * S_WA + n032 + 8 * nt + r0;
                        unsigned b0 = __float_as_uint(bp[0]);
                        unsigned b1 = __float_as_uint(bp[4 * S_WA]);
                        mma_tf32(acc2[0][nt], a[0], b0, b1);
                        mma_tf32(acc2[1][nt], a[1], b0, b1);
                    }
                }
                if (ch + 3 < NCH) issue_w1h(hf, ch + 3, (ch + 3) & 3);
            }
            __syncthreads();  // ring reads done; tz free to write

            // hoist GEMM3 prologue — copies land during t-store
            issue_w2h(hf, 0, 0);
            issue_w2h(hf, 1, 1);
            issue_w2h(hf, 2, 2);

            // t_half -> tz (tf32-rounded bits, GEMM3 A operand)
#pragma unroll
            for (int mt = 0; mt < 2; mt++)
#pragma unroll
                for (int nt = 0; nt < 4; nt++) {
                    int col = n032 + 8 * nt + cb;
#pragma unroll
                    for (int q = 0; q < 4; q++) {
                        int rr = m0 + 16 * mt + r0 + (q >> 1) * 8;
                        int cc = col + (q & 1);
                        float t = fmaxf(acc2[mt][nt][q] + __ldg(&b1[hf * 128 + cc]), 0.f);
                        tz[rr * S_H + cc] = __uint_as_float(f2tf(t));
                    }
                }
        }
        __syncthreads();

        // ---- GEMM3 half: acc3 += t_half @ W2[hf*128:+128, :] ----
        {
            const int NCH = 8;
            for (int ch = 0; ch < NCH; ch++) {
                if (ch < NCH - 2) cp_wait<2>();
                else if (ch == NCH - 2) cp_wait<1>();
                else cp_wait<0>();
                __syncthreads();
                const float* cur = wb + (ch & 3) * WB_SLOT;
#pragma unroll
                for (int ks = 0; ks < 2; ks++) {
                    int k0 = ch * 16 + ks * 8;
                    unsigned a[2][4];
#pragma unroll
                    for (int mt = 0; mt < 2; mt++) {
                        const float* ap = tz + (m0 + 16 * mt + r0) * S_H + k0 + qk;
                        a[mt][0] = __float_as_uint(ap[0]);
                        a[mt][1] = __float_as_uint(ap[8 * S_H]);
                        a[mt][2] = __float_as_uint(ap[4]);
                        a[mt][3] = __float_as_uint(ap[8 * S_H + 4]);
                    }
#pragma unroll
                    for (int nt = 0; nt < 4; nt++) {
                        const float* bp = cur + (ks * 8 + qk) * S_WA + n032 + 8 * nt + r0;
                        unsigned b0 = __float_as_uint(bp[0]);
                        unsigned b1 = __float_as_uint(bp[4 * S_WA]);
                        mma_tf32(acc3[0][nt], a[0], b0, b1);
                        mma_tf32(acc3[1][nt], a[1], b0, b1);
                    }
                }
                if (ch + 3 < NCH) issue_w2h(hf, ch + 3, (ch + 3) & 3);
            }
        }
        __syncthreads();  // tz reads done before next hf overwrites it
    }

    // z = acc3 + b2 + h  -> tz (t-half dead)
#pragma unroll
    for (int mt = 0; mt < 2; mt++)
#pragma unroll
        for (int nt = 0; nt < 4; nt++) {
            int col = n032 + 8 * nt + cb;
#pragma unroll
            for (int q = 0; q < 4; q++) {
                int rr = m0 + 16 * mt + r0 + (q >> 1) * 8;
                int cc = col + (q & 1);
                tz[rr * S_H + cc] = acc3[mt][nt][q] + __ldg(&b2[cc]) + hbuf[rr * S_H + cc];
            }
        }
    __syncthreads();

    // ---------------- LayerNorm2 -> global out ----------------
    for (int r = wid; r < TILE_E; r += 8) {
        int eg = e0 + r;
        float v[4], s = 0.f, s2 = 0.f;
#pragma unroll
        for (int q = 0; q < 4; q++) {
            v[q] = tz[r * S_H + lane + 32 * q];
            s += v[q];
            s2 += v[q] * v[q];
        }
#pragma unroll
        for (int off = 16; off > 0; off >>= 1) {
            s += __shfl_xor_sync(0xFFFFFFFF, s, off);
            s2 += __shfl_xor_sync(0xFFFFFFFF, s2, off);
        }
        float mu = s * (1.f / 128.f);
        float var = s2 * (1.f / 128.f) - mu * mu;
        float rinv = rsqrtf(var + EPS);
        if (eg < E) {
#pragma unroll
            for (int q = 0; q < 4; q++) {
                int c = lane + 32 * q;
                out[(size_t)eg * D_OUT + c] = (v[q] - mu) * rinv * __ldg(&g2[c]) + __ldg(&be2[c]);
            }
        }
    }
}

// ---------------------------------------------------------------------------
// launch
// ---------------------------------------------------------------------------
extern "C" void kernel_launch(void* const* d_in, const int* in_sizes, int n_in,
                              void* d_out, int out_size) {
    const void* p[16];
    int sz[16];
    int m = 0;
    for (int i = 0; i < n_in && m < 16; i++) {
        if (in_sizes[i] == 1) continue;
        p[m] = d_in[i];
        sz[m] = in_sizes[i];
        m++;
    }
    const float* x          = (const float*)p[0];
    const int*   edge_index = (const int*)p[1];
    const float* edge_attr  = (const float*)p[2];
    const float* mask       = (const float*)p[3];
    const float* We         = (const float*)p[4];
    const float* bE         = (const float*)p[5];
    const float* W1         = (const float*)p[6];
    const float* b1         = (const float*)p[7];
    const float* W2         = (const float*)p[8];
    const float* b2         = (const float*)p[9];
    const float* g1         = (const float*)p[10];
    const float* be1        = (const float*)p[11];
    const float* g2         = (const float*)p[12];
    const float* be2        = (const float*)p[13];

    const int N = sz[0] / 6;
    const int E = sz[3];

    float* out_node = (float*)d_out;                     // [N,134]
    float* out_edge = out_node + (size_t)N * D_NODEREP;  // [E,128]

    {
        int total = N * D_IN;
        zero_kernel<<<(total + 255) / 256, 256>>>(N);
    }
    {
        agg_kernel<<<(E + 7) / 8, 256>>>(edge_attr, mask, edge_index, E);
    }
    {
        const int smem = NP_SMEM_FLOATS * (int)sizeof(float);
        cudaFuncSetAttribute(nodeproj_kernel, cudaFuncAttributeMaxDynamicSharedMemorySize, smem);
        int blocks = (N + TILE_N - 1) / TILE_N;
        nodeproj_kernel<<<blocks, NPTHREADS, smem>>>(x, We, out_node, N);
    }
    {
        const int smem = E_SMEM_FLOATS * (int)sizeof(float);
        cudaFuncSetAttribute(edge_kernel, cudaFuncAttributeMaxDynamicSharedMemorySize, smem);
        int blocks = (E + TILE_E - 1) / TILE_E;
        edge_kernel<<<blocks, ETHREADS, smem>>>(edge_attr, edge_index,
                                                We, bE, W1, b1, W2, b2,
                                                g1, be1, g2, be2, out_edge, E);
    }
}

// round 10
// speedup vs baseline: 1.4081x; 1.0648x over previous
#include <cuda_runtime.h>
#include <cuda_bf16.h>
#include <cstdint>

// ---------------------------------------------------------------------------
// Problem constants
// ---------------------------------------------------------------------------
#define MAXN 50000
#define D_IN 128
#define D_OUT 128
#define D_NODEREP 134  // 128 + 6
#define DH 256
#define EPS 1e-5f

#define TILE_E 64
#define ETHREADS 256

// smem strides (floats) — conflict-free mma fragment LDS
#define S_H 132        // mod 32 = 4
#define S_WA 136       // 128-col weight chunks (mod 32 = 8)
#define S_WB 264       // 256-col weight chunks (mod 32 = 8)

// ---- edge kernel smem layout (floats) ----
#define HBUF_OFF 0
#define HBUF_FLOATS (TILE_E * S_H)             // 8448
#define TZ_OFF HBUF_FLOATS                     // featz / t-half overlay
#define TZ_FLOATS (TILE_E * S_H)               // 8448
#define WB_OFF (TZ_OFF + TZ_FLOATS)            // 16896
#define WB_SLOT 2176                           // 16 rows * 136
#define E_SMEM_FLOATS (WB_OFF + 4 * WB_SLOT)   // 25600 floats = 102.4 KB

// ---- node projection kernel ----
#define TILE_N 64
#define NPTHREADS 256
#define KPAD_P 144     // 134 padded to 16*9
#define NCH_P 9
#define S_P 164        // mod 32 = 4
#define NP_A_FLOATS (TILE_N * S_P)             // 10496
#define NP_WBUF 4224                           // 16 * 264
#define NP_SMEM_FLOATS (NP_A_FLOATS + 2 * NP_WBUF)  // 18944 floats = 75.8 KB

// Scratch (static device globals: no allocation allowed)
__device__ float g_agg[(size_t)MAXN * D_IN];
__device__ float g_den[MAXN];
__device__ float g_P[(size_t)MAXN * 256];      // [N][Pa(128) | Pb(128)]

// ---------------------------------------------------------------------------
// helpers
// ---------------------------------------------------------------------------
__device__ __forceinline__ unsigned f2tf(float f) {
    unsigned u;
    asm("cvt.rna.tf32.f32 %0, %1;" : "=r"(u) : "f"(f));
    return u;
}

__device__ __forceinline__ void mma_tf32(float* c, const unsigned* a,
                                         unsigned b0, unsigned b1) {
    asm volatile(
        "mma.sync.aligned.m16n8k8.row.col.f32.tf32.tf32.f32 "
        "{%0,%1,%2,%3},{%4,%5,%6,%7},{%8,%9},{%0,%1,%2,%3};\n"
        : "+f"(c[0]), "+f"(c[1]), "+f"(c[2]), "+f"(c[3])
        : "r"(a[0]), "r"(a[1]), "r"(a[2]), "r"(a[3]), "r"(b0), "r"(b1));
}

__device__ __forceinline__ void cp16(float* dst_smem, const float* src, bool pred) {
    unsigned d = (unsigned)__cvta_generic_to_shared(dst_smem);
    int sz = pred ? 16 : 0;
    asm volatile("cp.async.cg.shared.global [%0], [%1], 16, %2;\n"
                 :: "r"(d), "l"(src), "r"(sz));
}
__device__ __forceinline__ void cp_commit() {
    asm volatile("cp.async.commit_group;\n");
}
template <int N>
__device__ __forceinline__ void cp_wait() {
    asm volatile("cp.async.wait_group %0;\n" :: "n"(N));
}

// ---------------------------------------------------------------------------
// Kernel 1: zero the scratch (float4)
// ---------------------------------------------------------------------------
__global__ void zero_kernel(int N) {
    int idx = blockIdx.x * blockDim.x + threadIdx.x;
    int total4 = N * (D_IN / 4);
    if (idx < total4) ((float4*)g_agg)[idx] = make_float4(0.f, 0.f, 0.f, 0.f);
    if (idx < N) g_den[idx] = 0.f;
}

// ---------------------------------------------------------------------------
// Kernel 2: masked scatter-add aggregation (warp per edge, float4 atomics)
// ---------------------------------------------------------------------------
__global__ void agg_kernel(const float* __restrict__ edge_attr,
                           const float* __restrict__ mask,
                           const int* __restrict__ edge_index, int E) {
    int w = (blockIdx.x * blockDim.x + threadIdx.x) >> 5;
    int lane = threadIdx.x & 31;
    if (w >= E) return;
    float m = mask[w];
    if (m == 0.f) return;
    int col = edge_index[E + w];
    const float4* a = (const float4*)(edge_attr + (size_t)w * D_IN);
    float4* dst = (float4*)(g_agg + (size_t)col * D_IN);
    float4 v = a[lane];
    v.x *= m; v.y *= m; v.z *= m; v.w *= m;
    atomicAdd(dst + lane, v);
    if (lane == 0) atomicAdd(g_den + col, m);
}

// ---------------------------------------------------------------------------
// Kernel 3: node projection  P = node_rep @ [We_a | We_b]   (N x 256)
// Also materializes node_rep into out_node.
// ---------------------------------------------------------------------------
__global__ void __launch_bounds__(NPTHREADS, 2)
nodeproj_kernel(const float* __restrict__ x,
                const float* __restrict__ We,
                float* __restrict__ out_node, int N) {
    extern __shared__ float sm[];
    float* A = sm;
    float* wb = sm + NP_A_FLOATS;
    __shared__ float rden_s[TILE_N];

    const int tid = threadIdx.x;
    const int lane = tid & 31;
    const int wid = tid >> 5;
    const int n0blk = blockIdx.x * TILE_N;

    const int m0 = 16 * (wid >> 1);
    const int n0 = 128 * (wid & 1);
    const int r0 = lane >> 2;
    const int qk = lane & 3;
    const int cb = 2 * qk;

    auto issue_w = [&](int ch, int stage) {  // 16 rows x 256 cols (Wea|Web)
        float* dst = wb + stage * NP_WBUF;
        int kb = ch * 16;
#pragma unroll
        for (int j = 0; j < 4; j++) {
            int i = tid + j * NPTHREADS;
            int r = i >> 6;
            int c4 = (i & 63) * 4;
            int k = kb + r;
            const float* src = (c4 < 128)
                ? We + (size_t)k * D_OUT + c4
                : We + (size_t)(D_NODEREP + k) * D_OUT + (c4 - 128);
            cp16(dst + r * S_WB + c4, src, k < D_NODEREP);
        }
        cp_commit();
    };

    issue_w(0, 0);

    if (tid < TILE_N) {
        int n = n0blk + tid;
        float d = (n < N) ? g_den[n] : 0.f;
        rden_s[tid] = 1.0f / (d + 1.0f);
    }
    __syncthreads();

    for (int idx = tid; idx < TILE_N * KPAD_P; idx += NPTHREADS) {
        int e = idx / KPAD_P;
        int k = idx - e * KPAD_P;
        int n = n0blk + e;
        float v = 0.f;
        if (n < N && k < D_NODEREP) {
            if (k < D_IN)
                v = g_agg[(size_t)n * D_IN + k] * rden_s[e];
            else
                v = x[n * 6 + (k - D_IN)];
            out_node[(size_t)n * D_NODEREP + k] = v;
        }
        A[e * S_P + k] = v;
    }

    float acc[16][4];
#pragma unroll
    for (int nt = 0; nt < 16; nt++)
#pragma unroll
        for (int q = 0; q < 4; q++) acc[nt][q] = 0.f;

    for (int ch = 0; ch < NCH_P; ch++) {
        cp_wait<0>();
        __syncthreads();
        if (ch + 1 < NCH_P) issue_w(ch + 1, (ch + 1) & 1);
        const float* cur = wb + (ch & 1) * NP_WBUF;
#pragma unroll
        for (int ks = 0; ks < 2; ks++) {
            int k0 = ch * 16 + ks * 8;
            const float* ap = A + (m0 + r0) * S_P + k0 + qk;
            unsigned a[4];
            a[0] = f2tf(ap[0]);
            a[1] = f2tf(ap[8 * S_P]);
            a[2] = f2tf(ap[4]);
            a[3] = f2tf(ap[8 * S_P + 4]);
#pragma unroll
            for (int nt = 0; nt < 16; nt++) {
                const float* bp = cur + (ks * 8 + qk) * S_WB + n0 + 8 * nt + r0;
                mma_tf32(acc[nt], a, __float_as_uint(bp[0]),
                         __float_as_uint(bp[4 * S_WB]));
            }
        }
    }

#pragma unroll
    for (int nt = 0; nt < 16; nt++) {
        int col = n0 + 8 * nt + cb;
#pragma unroll
        for (int q = 0; q < 4; q++) {
            int rr = m0 + r0 + (q >> 1) * 8;
            int cc = col + (q & 1);
            int n = n0blk + rr;
            if (n < N) g_P[(size_t)n * 256 + cc] = acc[nt][q];
        }
    }
}

// ---------------------------------------------------------------------------
// Kernel 4: fused edge MLP with register-resident fused LayerNorms.
// 64 edges/block, 256 threads (8 warps, warp tile m32 x n32), 2 blocks/SM.
// Weight ring: 4 slots x 16 rows, depth-3 cp.async prefetch.
// Race-free ordering: wait -> barrier -> compute(ch) -> issue(ch+3).
// ---------------------------------------------------------------------------
__global__ void __launch_bounds__(ETHREADS, 2)
edge_kernel(const float* __restrict__ edge_attr,
            const int* __restrict__ edge_index,
            const float* __restrict__ We, const float* __restrict__ bE,
            const float* __restrict__ W1, const float* __restrict__ b1,
            const float* __restrict__ W2, const float* __restrict__ b2,
            const float* __restrict__ g1, const float* __restrict__ be1,
            const float* __restrict__ g2, const float* __restrict__ be2,
            float* __restrict__ out, int E) {
    extern __shared__ float sm[];
    float* hbuf = sm + HBUF_OFF;
    float* tz = sm + TZ_OFF;    // featz -> t-half overlay
    float* wb = sm + WB_OFF;
    __shared__ int rows_s[TILE_E], cols_s[TILE_E];
    __shared__ float red_s[TILE_E][4];    // per-row per-n-warp partial sums
    __shared__ float red_s2[TILE_E][4];
    __shared__ float mu_s[TILE_E], rinv_s[TILE_E];

    const int tid = threadIdx.x;
    const int lane = tid & 31;
    const int wid = tid >> 5;
    const int e0 = blockIdx.x * TILE_E;

    const int m0 = 32 * (wid & 1);     // 0 or 32
    const int warp_n = wid >> 1;       // 0..3
    const int n032 = 32 * warp_n;
    const int r0 = lane >> 2;
    const int qk = lane & 3;
    const int cb = 2 * qk;

    auto issue_wec = [&](int ch, int slot) {  // We_c rows 268+16ch..
        float* dst = wb + slot * WB_SLOT;
        int kb = ch * 16;
#pragma unroll
        for (int j = 0; j < 2; j++) {
            int i = tid + j * ETHREADS;
            int r = i >> 5, c4 = (i & 31) * 4;
            cp16(dst + r * S_WA + c4,
                 We + (size_t)(2 * D_NODEREP + kb + r) * D_OUT + c4, true);
        }
        cp_commit();
    };
    auto issue_w1h = [&](int hf, int ch, int slot) {  // W1 16 x 128 (col half)
        float* dst = wb + slot * WB_SLOT;
        int kb = ch * 16;
#pragma unroll
        for (int j = 0; j < 2; j++) {
            int i = tid + j * ETHREADS;
            int r = i >> 5, c4 = (i & 31) * 4;
            cp16(dst + r * S_WA + c4,
                 W1 + (size_t)(kb + r) * DH + hf * 128 + c4, true);
        }
        cp_commit();
    };
    auto issue_w2h = [&](int hf, int ch, int slot) {  // W2 16 x 128 (row half)
        float* dst = wb + slot * WB_SLOT;
        int kb = hf * 128 + ch * 16;
#pragma unroll
        for (int j = 0; j < 2; j++) {
            int i = tid + j * ETHREADS;
            int r = i >> 5, c4 = (i & 31) * 4;
            cp16(dst + r * S_WA + c4, W2 + (size_t)(kb + r) * D_OUT + c4, true);
        }
        cp_commit();
    };

    if (tid < TILE_E) {
        int eg = e0 + tid;
        rows_s[tid] = (eg < E) ? edge_index[eg] : 0;
        cols_s[tid] = (eg < E) ? edge_index[E + eg] : 0;
    }

    // GEMM1 prologue (depth 3) — overlaps the gathers below
    issue_wec(0, 0);
    issue_wec(1, 1);
    issue_wec(2, 2);

    // edge_attr tile -> tz (featz), float4 coalesced, PRE-ROUNDED to tf32
    for (int idx = tid; idx < TILE_E * 32; idx += ETHREADS) {
        int e = idx >> 5;
        int c4 = (idx & 31) * 4;
        int eg = e0 + e;
        float4 v = make_float4(0.f, 0.f, 0.f, 0.f);
        if (eg < E) v = *(const float4*)(edge_attr + (size_t)eg * D_IN + c4);
        v.x = __uint_as_float(f2tf(v.x));
        v.y = __uint_as_float(f2tf(v.y));
        v.z = __uint_as_float(f2tf(v.z));
        v.w = __uint_as_float(f2tf(v.w));
        *(float4*)(tz + e * S_H + c4) = v;
    }
    __syncthreads();  // rows_s/cols_s ready

    // hbuf = Pa[row] + Pb[col]  (float4 gather from L2-resident P, fp32)
    for (int idx = tid; idx < TILE_E * 32; idx += ETHREADS) {
        int e = idx >> 5;
        int c4 = (idx & 31) * 4;
        float4 pa = *(const float4*)(g_P + (size_t)rows_s[e] * 256 + c4);
        float4 pb = *(const float4*)(g_P + (size_t)cols_s[e] * 256 + 128 + c4);
        pa.x += pb.x; pa.y += pb.y; pa.z += pb.z; pa.w += pb.w;
        *(float4*)(hbuf + e * S_H + c4) = pa;
    }

    // ================= GEMM1: featz[64,128] @ We_c[128,128] ==============
    float acc1[2][4][4];
#pragma unroll
    for (int mt = 0; mt < 2; mt++)
#pragma unroll
        for (int nt = 0; nt < 4; nt++)
#pragma unroll
            for (int q = 0; q < 4; q++) acc1[mt][nt][q] = 0.f;

    {
        const int NCH = 8;
        for (int ch = 0; ch < NCH; ch++) {
            if (ch < NCH - 2) cp_wait<2>();
            else if (ch == NCH - 2) cp_wait<1>();
            else cp_wait<0>();
            __syncthreads();
            const float* cur = wb + (ch & 3) * WB_SLOT;
#pragma unroll
            for (int ks = 0; ks < 2; ks++) {
                int k0 = ch * 16 + ks * 8;
                unsigned a[2][4];
#pragma unroll
                for (int mt = 0; mt < 2; mt++) {
                    const float* ap = tz + (m0 + 16 * mt + r0) * S_H + k0 + qk;
                    a[mt][0] = __float_as_uint(ap[0]);
                    a[mt][1] = __float_as_uint(ap[8 * S_H]);
                    a[mt][2] = __float_as_uint(ap[4]);
                    a[mt][3] = __float_as_uint(ap[8 * S_H + 4]);
                }
#pragma unroll
                for (int nt = 0; nt < 4; nt++) {
                    const float* bp = cur + (ks * 8 + qk) * S_WA + n032 + 8 * nt + r0;
                    unsigned b0 = __float_as_uint(bp[0]);
                    unsigned b1w = __float_as_uint(bp[4 * S_WA]);
                    mma_tf32(acc1[0][nt], a[0], b0, b1w);
                    mma_tf32(acc1[1][nt], a[1], b0, b1w);
                }
            }
            if (ch + 3 < NCH) issue_wec(ch + 3, (ch + 3) & 3);
        }
    }

    // GEMM2(hf=0) prologue — slots 0,1,2 last read at ch 4,5,6 (all done)
    issue_w1h(0, 0, 0);
    issue_w1h(0, 1, 1);
    issue_w1h(0, 2, 2);

    // ---- GEMM1 epilogue with fused LN1 (register-resident) ----
    // acc1 = acc1 + bE + featz(tz) + P(hbuf); per-row stats via shfl + redbuf
#pragma unroll
    for (int mt = 0; mt < 2; mt++)
#pragma unroll
        for (int nt = 0; nt < 4; nt++) {
            int col = n032 + 8 * nt + cb;
            float2 bev = *(const float2*)(bE + col);
#pragma unroll
            for (int rh = 0; rh < 2; rh++) {
                int rr = m0 + 16 * mt + r0 + 8 * rh;
                float2 fz = *(float2*)(tz + rr * S_H + col);
                float2 pv = *(float2*)(hbuf + rr * S_H + col);
                acc1[mt][nt][2 * rh + 0] += bev.x + fz.x + pv.x;
                acc1[mt][nt][2 * rh + 1] += bev.y + fz.y + pv.y;
            }
        }
#pragma unroll
    for (int mt = 0; mt < 2; mt++)
#pragma unroll
        for (int rh = 0; rh < 2; rh++) {
            float s = 0.f, s2 = 0.f;
#pragma unroll
            for (int nt = 0; nt < 4; nt++)
#pragma unroll
                for (int b = 0; b < 2; b++) {
                    float v = acc1[mt][nt][2 * rh + b];
                    s += v; s2 += v * v;
                }
            s += __shfl_xor_sync(0xFFFFFFFF, s, 1);
            s += __shfl_xor_sync(0xFFFFFFFF, s, 2);
            s2 += __shfl_xor_sync(0xFFFFFFFF, s2, 1);
            s2 += __shfl_xor_sync(0xFFFFFFFF, s2, 2);
            if (qk == 0) {
                int rr = m0 + 16 * mt + r0 + 8 * rh;
                red_s[rr][warp_n] = s;
                red_s2[rr][warp_n] = s2;
            }
        }
    __syncthreads();
    if (tid < TILE_E) {
        float s = red_s[tid][0] + red_s[tid][1] + red_s[tid][2] + red_s[tid][3];
        float s2 = red_s2[tid][0] + red_s2[tid][1] + red_s2[tid][2] + red_s2[tid][3];
        float mu = s * (1.f / 128.f);
        float var = s2 * (1.f / 128.f) - mu * mu;
        mu_s[tid] = mu;
        rinv_s[tid] = rsqrtf(var + EPS);
    }
    __syncthreads();
    // normalize from regs, store h (tf32-rounded) to hbuf as float2
#pragma unroll
    for (int mt = 0; mt < 2; mt++)
#pragma unroll
        for (int nt = 0; nt < 4; nt++) {
            int col = n032 + 8 * nt + cb;
            float2 gv = *(const float2*)(g1 + col);
            float2 bv = *(const float2*)(be1 + col);
#pragma unroll
            for (int rh = 0; rh < 2; rh++) {
                int rr = m0 + 16 * mt + r0 + 8 * rh;
                float mu = mu_s[rr], ri = rinv_s[rr];
                float h0 = (acc1[mt][nt][2 * rh + 0] - mu) * ri * gv.x + bv.x;
                float h1 = (acc1[mt][nt][2 * rh + 1] - mu) * ri * gv.y + bv.y;
                float2 hv;
                hv.x = __uint_as_float(f2tf(h0));
                hv.y = __uint_as_float(f2tf(h1));
                *(float2*)(hbuf + rr * S_H + col) = hv;
            }
        }

    // ============ GEMM2+GEMM3 in two 128-halves, acc3 persistent =========
    float acc3[2][4][4];
#pragma unroll
    for (int mt = 0; mt < 2; mt++)
#pragma unroll
        for (int nt = 0; nt < 4; nt++)
#pragma unroll
            for (int q = 0; q < 4; q++) acc3[mt][nt][q] = 0.f;

#pragma unroll 1
    for (int hf = 0; hf < 2; hf++) {
        // ---- GEMM2 half: t_half = relu(h @ W1[:, hf*128:+128] + b1h) ----
        {
            float acc2[2][4][4];
#pragma unroll
            for (int mt = 0; mt < 2; mt++)
#pragma unroll
                for (int nt = 0; nt < 4; nt++)
#pragma unroll
                    for (int q = 0; q < 4; q++) acc2[mt][nt][q] = 0.f;

            if (hf) {  // hf=0 prologue hoisted before LN1
                issue_w1h(hf, 0, 0);
                issue_w1h(hf, 1, 1);
                issue_w1h(hf, 2, 2);
            }
            const int NCH = 8;
            for (int ch = 0; ch < NCH; ch++) {
                if (ch < NCH - 2) cp_wait<2>();
                else if (ch == NCH - 2) cp_wait<1>();
                else cp_wait<0>();
                __syncthreads();
                const float* cur = wb + (ch & 3) * WB_SLOT;
#pragma unroll
                for (int ks = 0; ks < 2; ks++) {
                    int k0 = ch * 16 + ks * 8;
                    unsigned a[2][4];
#pragma unroll
                    for (int mt = 0; mt < 2; mt++) {
                        const float* ap = hbuf + (m0 + 16 * mt + r0) * S_H + k0 + qk;
                        a[mt][0] = __float_as_uint(ap[0]);
                        a[mt][1] = __float_as_uint(ap[8 * S_H]);
                        a[mt][2] = __float_as_uint(ap[4]);
                        a[mt][3] = __float_as_uint(ap[8 * S_H + 4]);
                    }
#pragma unroll
                    for (int nt = 0; nt < 4; nt++) {
                        const float* bp = cur + (ks * 8 + qk) * S_WA + n032 + 8 * nt + r0;
                        unsigned b0 = __float_as_uint(bp[0]);
                        unsigned b1w = __float_as_uint(bp[4 * S_WA]);
                        mma_tf32(acc2[0][nt], a[0], b0, b1w);
                        mma_tf32(acc2[1][nt], a[1], b0, b1w);
                    }
                }
                if (ch + 3 < NCH) issue_w1h(hf, ch + 3, (ch + 3) & 3);
            }
            __syncthreads();  // ring reads done; tz free to write

            // hoist GEMM3 prologue — copies land during t-store
            issue_w2h(hf, 0, 0);
            issue_w2h(hf, 1, 1);
            issue_w2h(hf, 2, 2);

            // t_half -> tz (tf32-rounded bits, GEMM3 A operand), float2
#pragma unroll
            for (int mt = 0; mt < 2; mt++)
#pragma unroll
                for (int nt = 0; nt < 4; nt++) {
                    int col = n032 + 8 * nt + cb;
                    float2 b1v = *(const float2*)(b1 + hf * 128 + col);
#pragma unroll
                    for (int rh = 0; rh < 2; rh++) {
                        int rr = m0 + 16 * mt + r0 + 8 * rh;
                        float t0 = fmaxf(acc2[mt][nt][2 * rh + 0] + b1v.x, 0.f);
                        float t1 = fmaxf(acc2[mt][nt][2 * rh + 1] + b1v.y, 0.f);
                        float2 tv;
                        tv.x = __uint_as_float(f2tf(t0));
                        tv.y = __uint_as_float(f2tf(t1));
                        *(float2*)(tz + rr * S_H + col) = tv;
                    }
                }
        }
        __syncthreads();

        // ---- GEMM3 half: acc3 += t_half @ W2[hf*128:+128, :] ----
        {
            const int NCH = 8;
            for (int ch = 0; ch < NCH; ch++) {
                if (ch < NCH - 2) cp_wait<2>();
                else if (ch == NCH - 2) cp_wait<1>();
                else cp_wait<0>();
                __syncthreads();
                const float* cur = wb + (ch & 3) * WB_SLOT;
#pragma unroll
                for (int ks = 0; ks < 2; ks++) {
                    int k0 = ch * 16 + ks * 8;
                    unsigned a[2][4];
#pragma unroll
                    for (int mt = 0; mt < 2; mt++) {
                        const float* ap = tz + (m0 + 16 * mt + r0) * S_H + k0 + qk;
                        a[mt][0] = __float_as_uint(ap[0]);
                        a[mt][1] = __float_as_uint(ap[8 * S_H]);
                        a[mt][2] = __float_as_uint(ap[4]);
                        a[mt][3] = __float_as_uint(ap[8 * S_H + 4]);
                    }
#pragma unroll
                    for (int nt = 0; nt < 4; nt++) {
                        const float* bp = cur + (ks * 8 + qk) * S_WA + n032 + 8 * nt + r0;
                        unsigned b0 = __float_as_uint(bp[0]);
                        unsigned b1w = __float_as_uint(bp[4 * S_WA]);
                        mma_tf32(acc3[0][nt], a[0], b0, b1w);
                        mma_tf32(acc3[1][nt], a[1], b0, b1w);
                    }
                }
                if (ch + 3 < NCH) issue_w2h(hf, ch + 3, (ch + 3) & 3);
            }
        }
        __syncthreads();  // tz reads done before next hf overwrites it
    }

    // ---- GEMM3 epilogue with fused LN2 (register-resident) -> global ----
    // z = acc3 + b2 + h(hbuf)
#pragma unroll
    for (int mt = 0; mt < 2; mt++)
#pragma unroll
        for (int nt = 0; nt < 4; nt++) {
            int col = n032 + 8 * nt + cb;
            float2 b2v = *(const float2*)(b2 + col);
#pragma unroll
            for (int rh = 0; rh < 2; rh++) {
                int rr = m0 + 16 * mt + r0 + 8 * rh;
                float2 hv = *(float2*)(hbuf + rr * S_H + col);
                acc3[mt][nt][2 * rh + 0] += b2v.x + hv.x;
                acc3[mt][nt][2 * rh + 1] += b2v.y + hv.y;
            }
        }
#pragma unroll
    for (int mt = 0; mt < 2; mt++)
#pragma unroll
        for (int rh = 0; rh < 2; rh++) {
            float s = 0.f, s2 = 0.f;
#pragma unroll
            for (int nt = 0; nt < 4; nt++)
#pragma unroll
                for (int b = 0; b < 2; b++) {
                    float v = acc3[mt][nt][2 * rh + b];
                    s += v; s2 += v * v;
                }
            s += __shfl_xor_sync(0xFFFFFFFF, s, 1);
            s += __shfl_xor_sync(0xFFFFFFFF, s, 2);
            s2 += __shfl_xor_sync(0xFFFFFFFF, s2, 1);
            s2 += __shfl_xor_sync(0xFFFFFFFF, s2, 2);
            if (qk == 0) {
                int rr = m0 + 16 * mt + r0 + 8 * rh;
                red_s[rr][warp_n] = s;
                red_s2[rr][warp_n] = s2;
            }
        }
    __syncthreads();
    if (tid < TILE_E) {
        float s = red_s[tid][0] + red_s[tid][1] + red_s[tid][2] + red_s[tid][3];
        float s2 = red_s2[tid][0] + red_s2[tid][1] + red_s2[tid][2] + red_s2[tid][3];
        float mu = s * (1.f / 128.f);
        float var = s2 * (1.f / 128.f) - mu * mu;
        mu_s[tid] = mu;
        rinv_s[tid] = rsqrtf(var + EPS);
    }
    __syncthreads();
#pragma unroll
    for (int mt = 0; mt < 2; mt++)
#pragma unroll
        for (int nt = 0; nt < 4; nt++) {
            int col = n032 + 8 * nt + cb;
            float2 gv = *(const float2*)(g2 + col);
            float2 bv = *(const float2*)(be2 + col);
#pragma unroll
            for (int rh = 0; rh < 2; rh++) {
                int rr = m0 + 16 * mt + r0 + 8 * rh;
                int eg = e0 + rr;
                if (eg < E) {
                    float mu = mu_s[rr], ri = rinv_s[rr];
                    float2 ov;
                    ov.x = (acc3[mt][nt][2 * rh + 0] - mu) * ri * gv.x + bv.x;
                    ov.y = (acc3[mt][nt][2 * rh + 1] - mu) * ri * gv.y + bv.y;
                    *(float2*)(out + (size_t)eg * D_OUT + col) = ov;
                }
            }
        }
}

// ---------------------------------------------------------------------------
// launch
// ---------------------------------------------------------------------------
extern "C" void kernel_launch(void* const* d_in, const int* in_sizes, int n_in,
                              void* d_out, int out_size) {
    const void* p[16];
    int sz[16];
    int m = 0;
    for (int i = 0; i < n_in && m < 16; i++) {
        if (in_sizes[i] == 1) continue;
        p[m] = d_in[i];
        sz[m] = in_sizes[i];
        m++;
    }
    const float* x          = (const float*)p[0];
    const int*   edge_index = (const int*)p[1];
    const float* edge_attr  = (const float*)p[2];
    const float* mask       = (const float*)p[3];
    const float* We         = (const float*)p[4];
    const float* bE         = (const float*)p[5];
    const float* W1         = (const float*)p[6];
    const float* b1         = (const float*)p[7];
    const float* W2         = (const float*)p[8];
    const float* b2         = (const float*)p[9];
    const float* g1         = (const float*)p[10];
    const float* be1        = (const float*)p[11];
    const float* g2         = (const float*)p[12];
    const float* be2        = (const float*)p[13];

    const int N = sz[0] / 6;
    const int E = sz[3];

    float* out_node = (float*)d_out;                     // [N,134]
    float* out_edge = out_node + (size_t)N * D_NODEREP;  // [E,128]

    {
        int total4 = N * (D_IN / 4);
        zero_kernel<<<(total4 + 255) / 256, 256>>>(N);
    }
    {
        agg_kernel<<<(E + 7) / 8, 256>>>(edge_attr, mask, edge_index, E);
    }
    {
        const int smem = NP_SMEM_FLOATS * (int)sizeof(float);
        cudaFuncSetAttribute(nodeproj_kernel, cudaFuncAttributeMaxDynamicSharedMemorySize, smem);
        int blocks = (N + TILE_N - 1) / TILE_N;
        nodeproj_kernel<<<blocks, NPTHREADS, smem>>>(x, We, out_node, N);
    }
    {
        const int smem = E_SMEM_FLOATS * (int)sizeof(float);
        cudaFuncSetAttribute(edge_kernel, cudaFuncAttributeMaxDynamicSharedMemorySize, smem);
        int blocks = (E + TILE_E - 1) / TILE_E;
        edge_kernel<<<blocks, ETHREADS, smem>>>(edge_attr, edge_index,
                                                We, bE, W1, b1, W2, b2,
                                                g1, be1, g2, be2, out_edge, E);
    }
}